// round 5
// baseline (speedup 1.0000x reference)
#include <cuda_runtime.h>
#include <cuda_bf16.h>

#define BATCH 2
#define SEQ   2048
#define HID   2048
#define NHEAD 16
#define DK    128
#define MROWS (BATCH*SEQ)

// ---------------- scratch (allocation-free) ----------------
__device__ __nv_bfloat16 g_x_hi[(size_t)MROWS * HID];
__device__ __nv_bfloat16 g_x_lo[(size_t)MROWS * HID];
__device__ __nv_bfloat16 g_w_hi[4][(size_t)HID * HID];
__device__ __nv_bfloat16 g_w_lo[4][(size_t)HID * HID];
__device__ float g_q [(size_t)MROWS * HID];
__device__ float g_k [(size_t)MROWS * HID];
__device__ float g_v [(size_t)MROWS * HID];
__device__ __nv_bfloat16 g_ao_hi[(size_t)MROWS * HID];
__device__ __nv_bfloat16 g_ao_lo[(size_t)MROWS * HID];

// ---------------- PTX helpers (sm_80-era, nothing 'a'-gated) ----------------
__device__ __forceinline__ unsigned smem_u32(const void* p) {
    unsigned a;
    asm("{ .reg .u64 t; cvta.to.shared.u64 t, %1; cvt.u32.u64 %0, t; }" : "=r"(a) : "l"(p));
    return a;
}
__device__ __forceinline__ void cp16(unsigned s, const void* g) {
    asm volatile("cp.async.cg.shared.global [%0], [%1], 16;" :: "r"(s), "l"(g));
}
#define CP_COMMIT() asm volatile("cp.async.commit_group;" ::: "memory")
#define CP_WAIT(n)  asm volatile("cp.async.wait_group %0;" :: "n"(n) : "memory")

__device__ __forceinline__ void ldm4(unsigned* r, unsigned addr) {
    asm volatile("ldmatrix.sync.aligned.m8n8.x4.shared.b16 {%0,%1,%2,%3}, [%4];"
        : "=r"(r[0]), "=r"(r[1]), "=r"(r[2]), "=r"(r[3]) : "r"(addr));
}
__device__ __forceinline__ void mma_bf16(float* d, const unsigned* a, const unsigned* b) {
    asm volatile(
        "mma.sync.aligned.m16n8k16.row.col.f32.bf16.bf16.f32 "
        "{%0,%1,%2,%3}, {%4,%5,%6,%7}, {%8,%9}, {%0,%1,%2,%3};"
        : "+f"(d[0]), "+f"(d[1]), "+f"(d[2]), "+f"(d[3])
        : "r"(a[0]), "r"(a[1]), "r"(a[2]), "r"(a[3]), "r"(b[0]), "r"(b[1]));
}

// ---------------- fp32 -> bf16 hi/lo split ----------------
__global__ __launch_bounds__(256)
void split_bf16(const float* __restrict__ in, __nv_bfloat16* __restrict__ hi,
                __nv_bfloat16* __restrict__ lo, int n4)
{
    int i = blockIdx.x * 256 + threadIdx.x;
    if (i >= n4) return;
    float4 v = ((const float4*)in)[i];
    __nv_bfloat16 h0 = __float2bfloat16(v.x);
    __nv_bfloat16 h1 = __float2bfloat16(v.y);
    __nv_bfloat16 h2 = __float2bfloat16(v.z);
    __nv_bfloat16 h3 = __float2bfloat16(v.w);
    __nv_bfloat16 l0 = __float2bfloat16(v.x - __bfloat162float(h0));
    __nv_bfloat16 l1 = __float2bfloat16(v.y - __bfloat162float(h1));
    __nv_bfloat16 l2 = __float2bfloat16(v.z - __bfloat162float(h2));
    __nv_bfloat16 l3 = __float2bfloat16(v.w - __bfloat162float(h3));
    __nv_bfloat162* hp = (__nv_bfloat162*)hi;
    __nv_bfloat162* lp = (__nv_bfloat162*)lo;
    hp[2*i+0] = __nv_bfloat162(h0, h1);
    hp[2*i+1] = __nv_bfloat162(h2, h3);
    lp[2*i+0] = __nv_bfloat162(l0, l1);
    lp[2*i+1] = __nv_bfloat162(l2, l3);
}

// ---------------- mma.sync GEMM: C[m][n] = sum_k A[m][k] B[n][k] ----------------
// A = Ahi+Alo, B = Bhi+Blo (bf16); 3-product fp32 accumulation.
// 128x128 tile, BK=32, 8 warps (2m x 4n, warp tile 64x32).
// 4-stage cp.async pipeline, ONE barrier per iteration, wait_group 2
// (3-iteration lookahead hides DRAM-tier latency). Unconditional empty
// commit_group in the tail keeps the wait-count invariant.
// Smem rows padded to 80B: stride 20 words => conflict-free ldmatrix.
#define BKI 32
#define ROWB 80
#define ARR_BYTES (128 * ROWB)        // 10240
#define OFF_AHI 0
#define OFF_ALO (1 * ARR_BYTES)
#define OFF_BHI (2 * ARR_BYTES)
#define OFF_BLO (3 * ARR_BYTES)
#define STG_BYTES (4 * ARR_BYTES)     // 40960
#define NSTAGE 4
#define GEMM_SMEM (NSTAGE * STG_BYTES) // 163840
#define NKIT (HID / BKI)              // 64

__device__ __forceinline__ void gemm_load_stage(
    const __nv_bfloat16* __restrict__ Ahi, const __nv_bfloat16* __restrict__ Alo,
    const __nv_bfloat16* __restrict__ Bhi, const __nv_bfloat16* __restrict__ Blo,
    int rowBase, int colBase, int k0, unsigned stage, int t)
{
    const int r    = t >> 1;          // 0..127
    const int half = t & 1;           // chunk pair 0/1
    const size_t ga = (size_t)(rowBase + r) * HID + k0 + half * 16;
    const size_t gb = (size_t)(colBase + r) * HID + k0 + half * 16;
    const unsigned so = r * ROWB + half * 32;
    cp16(stage + OFF_AHI + so,      Ahi + ga);
    cp16(stage + OFF_AHI + so + 16, Ahi + ga + 8);
    cp16(stage + OFF_ALO + so,      Alo + ga);
    cp16(stage + OFF_ALO + so + 16, Alo + ga + 8);
    cp16(stage + OFF_BHI + so,      Bhi + gb);
    cp16(stage + OFF_BHI + so + 16, Bhi + gb + 8);
    cp16(stage + OFF_BLO + so,      Blo + gb);
    cp16(stage + OFF_BLO + so + 16, Blo + gb + 8);
}

__global__ __launch_bounds__(256)
void gemm_mma(const __nv_bfloat16* __restrict__ Ahi, const __nv_bfloat16* __restrict__ Alo,
              const __nv_bfloat16* __restrict__ Bhi, const __nv_bfloat16* __restrict__ Blo,
              float* __restrict__ C, const float* __restrict__ freqs, int do_rope)
{
    extern __shared__ char sm[];
    const unsigned smem = smem_u32(sm);
    const int t    = threadIdx.x;
    const int wid  = t >> 5;
    const int lane = t & 31;
    const int wm   = wid & 1;          // 0..1 (64-row groups)
    const int wn   = wid >> 1;         // 0..3 (32-col groups)
    const int rowBase = blockIdx.y * 128;
    const int colBase = blockIdx.x * 128;

    const unsigned aOff = (wm * 64 + (lane & 15)) * ROWB + ((lane >> 4) & 1) * 16;
    const unsigned bOff = (wn * 32 + ((lane >> 4) & 1) * 8 + (lane & 7)) * ROWB
                        + ((lane >> 3) & 1) * 16;

    float acc[4][4][4];
    #pragma unroll
    for (int mt = 0; mt < 4; ++mt)
        #pragma unroll
        for (int nt = 0; nt < 4; ++nt)
            #pragma unroll
            for (int c = 0; c < 4; ++c) acc[mt][nt][c] = 0.f;

    // prologue: fill NSTAGE-1 stages
    #pragma unroll
    for (int s = 0; s < NSTAGE - 1; ++s) {
        gemm_load_stage(Ahi, Alo, Bhi, Blo, rowBase, colBase, s * BKI,
                        smem + s * STG_BYTES, t);
        CP_COMMIT();
    }

    for (int it = 0; it < NKIT; ++it) {
        CP_WAIT(NSTAGE - 2);          // stage `it` resident
        __syncthreads();              // all warps past wait; stage (it-1) reads done

        const int ld = it + NSTAGE - 1;
        if (ld < NKIT)
            gemm_load_stage(Ahi, Alo, Bhi, Blo, rowBase, colBase, ld * BKI,
                            smem + (ld & (NSTAGE - 1)) * STG_BYTES, t);
        CP_COMMIT();                  // unconditional: keeps group-count invariant

        const unsigned cur = smem + (it & (NSTAGE - 1)) * STG_BYTES;
        #pragma unroll
        for (int ks = 0; ks < 2; ++ks) {
            const unsigned kofs = ks * 32;
            unsigned ah[4][4], al[4][4], bh[2][4], bl[2][4];
            #pragma unroll
            for (int mt = 0; mt < 4; ++mt) {
                ldm4(ah[mt], cur + OFF_AHI + aOff + mt * (16 * ROWB) + kofs);
                ldm4(al[mt], cur + OFF_ALO + aOff + mt * (16 * ROWB) + kofs);
            }
            #pragma unroll
            for (int p = 0; p < 2; ++p) {
                ldm4(bh[p], cur + OFF_BHI + bOff + p * (16 * ROWB) + kofs);
                ldm4(bl[p], cur + OFF_BLO + bOff + p * (16 * ROWB) + kofs);
            }
            // product-major: same-acc chains separated by 16 independent MMAs
            #pragma unroll
            for (int mt = 0; mt < 4; ++mt)
                #pragma unroll
                for (int nt = 0; nt < 4; ++nt)
                    mma_bf16(acc[mt][nt], ah[mt], &bh[nt >> 1][(nt & 1) * 2]);
            #pragma unroll
            for (int mt = 0; mt < 4; ++mt)
                #pragma unroll
                for (int nt = 0; nt < 4; ++nt)
                    mma_bf16(acc[mt][nt], ah[mt], &bl[nt >> 1][(nt & 1) * 2]);
            #pragma unroll
            for (int mt = 0; mt < 4; ++mt)
                #pragma unroll
                for (int nt = 0; nt < 4; ++nt)
                    mma_bf16(acc[mt][nt], al[mt], &bh[nt >> 1][(nt & 1) * 2]);
        }
    }

    // epilogue: lane holds rows (g, g+8), col pair tig*2 per tile
    const int g   = lane >> 2;
    const int tig = lane & 3;
    #pragma unroll
    for (int mt = 0; mt < 4; ++mt) {
        #pragma unroll
        for (int nt = 0; nt < 4; ++nt) {
            const int m0 = rowBase + wm * 64 + mt * 16 + g;
            const int n0 = colBase + wn * 32 + nt * 8 + tig * 2;
            float v0 = acc[mt][nt][0], v1 = acc[mt][nt][1];
            float v2 = acc[mt][nt][2], v3 = acc[mt][nt][3];
            if (do_rope) {
                const int d = n0 & (DK - 1);     // even
                const int s0 = m0 & (SEQ - 1);
                const int s1 = (m0 + 8) & (SEQ - 1);
                const float cs0 = freqs[s0 * DK + d], sn0 = freqs[s0 * DK + d + 1];
                const float cs1 = freqs[s1 * DK + d], sn1 = freqs[s1 * DK + d + 1];
                *(float2*)(C + (size_t)m0 * HID + n0) =
                    make_float2(v0 * cs0 - v1 * sn0, v0 * sn0 + v1 * cs0);
                *(float2*)(C + (size_t)(m0 + 8) * HID + n0) =
                    make_float2(v2 * cs1 - v3 * sn1, v2 * sn1 + v3 * cs1);
            } else {
                *(float2*)(C + (size_t)m0 * HID + n0)       = make_float2(v0, v1);
                *(float2*)(C + (size_t)(m0 + 8) * HID + n0) = make_float2(v2, v3);
            }
        }
    }
}

// ---------------------------------------------------------------------------
// Flash attention, fp32, causal (proven kernel); epilogue emits bf16 hi/lo.
// ---------------------------------------------------------------------------
#define ATTN_SMEM_FLOATS (128*68 + 128*68 + 64*132 + 64*68)

__global__ __launch_bounds__(256)
void attn_flash(const float* __restrict__ q, const float* __restrict__ k,
                const float* __restrict__ v,
                __nv_bfloat16* __restrict__ ohi, __nv_bfloat16* __restrict__ olo)
{
    extern __shared__ float smf[];
    float* Qt = smf;                // [128][68]
    float* Kt = Qt + 128*68;        // [128][68]
    float* Vs = Kt + 128*68;        // [64][132]
    float* Ps = Vs + 64*132;        // [64][68]

    const int t  = threadIdx.x;
    const int tx = t & 15;
    const int ty = t >> 4;
    const int qt = blockIdx.x;
    const int b  = blockIdx.y >> 4;
    const int h  = blockIdx.y & 15;
    const int q0 = qt * 64;

    const size_t headoff = (size_t)b * SEQ * HID + (size_t)h * DK;
    const float* qb = q + headoff;
    const float* kb = k + headoff;
    const float* vb = v + headoff;

    for (int l = t; l < 64*32; l += 256) {
        const int s  = l >> 5;
        const int d0 = (l & 31) << 2;
        float4 val = *(const float4*)(qb + (size_t)(q0 + s) * HID + d0);
        Qt[(d0+0)*68 + s] = val.x;
        Qt[(d0+1)*68 + s] = val.y;
        Qt[(d0+2)*68 + s] = val.z;
        Qt[(d0+3)*68 + s] = val.w;
    }

    float m_i[4], l_i[4], oacc[4][8];
    #pragma unroll
    for (int i = 0; i < 4; ++i) {
        m_i[i] = -1e30f; l_i[i] = 0.f;
        #pragma unroll
        for (int c = 0; c < 8; ++c) oacc[i][c] = 0.f;
    }
    const float scale = 0.088388347648318447f;

    for (int j = 0; j <= qt; ++j) {
        const int kbase = j * 64;
        __syncthreads();
        for (int l = t; l < 64*32; l += 256) {
            const int s  = l >> 5;
            const int d0 = (l & 31) << 2;
            float4 kv = *(const float4*)(kb + (size_t)(kbase + s) * HID + d0);
            Kt[(d0+0)*68 + s] = kv.x;
            Kt[(d0+1)*68 + s] = kv.y;
            Kt[(d0+2)*68 + s] = kv.z;
            Kt[(d0+3)*68 + s] = kv.w;
            float4 vv = *(const float4*)(vb + (size_t)(kbase + s) * HID + d0);
            *(float4*)&Vs[s*132 + d0] = vv;
        }
        __syncthreads();

        float sacc[4][4];
        #pragma unroll
        for (int i = 0; i < 4; ++i)
            #pragma unroll
            for (int jj = 0; jj < 4; ++jj) sacc[i][jj] = 0.f;

        #pragma unroll 4
        for (int d = 0; d < 128; ++d) {
            float4 qv = *(const float4*)&Qt[d*68 + ty*4];
            float4 kv = *(const float4*)&Kt[d*68 + tx*4];
            float qr[4] = {qv.x,qv.y,qv.z,qv.w};
            float kr[4] = {kv.x,kv.y,kv.z,kv.w};
            #pragma unroll
            for (int i = 0; i < 4; ++i)
                #pragma unroll
                for (int jj = 0; jj < 4; ++jj)
                    sacc[i][jj] = fmaf(qr[i], kr[jj], sacc[i][jj]);
        }

        const bool diag = (j == qt);
        #pragma unroll
        for (int i = 0; i < 4; ++i) {
            float sv[4];
            #pragma unroll
            for (int jj = 0; jj < 4; ++jj) {
                float x = sacc[i][jj] * scale;
                if (diag && (tx*4 + jj > ty*4 + i)) x = -1e30f;
                sv[jj] = x;
            }
            float rm = fmaxf(fmaxf(sv[0], sv[1]), fmaxf(sv[2], sv[3]));
            #pragma unroll
            for (int off = 8; off > 0; off >>= 1)
                rm = fmaxf(rm, __shfl_xor_sync(0xffffffffu, rm, off, 16));
            const float mnew = fmaxf(m_i[i], rm);
            const float corr = __expf(m_i[i] - mnew);
            float rs = 0.f;
            const int prow = (ty*4 + i)*68 + tx*4;
            #pragma unroll
            for (int jj = 0; jj < 4; ++jj) {
                const float p = __expf(sv[jj] - mnew);
                Ps[prow + jj] = p;
                rs += p;
            }
            #pragma unroll
            for (int off = 8; off > 0; off >>= 1)
                rs += __shfl_xor_sync(0xffffffffu, rs, off, 16);
            l_i[i] = l_i[i] * corr + rs;
            m_i[i] = mnew;
            #pragma unroll
            for (int c = 0; c < 8; ++c) oacc[i][c] *= corr;
        }
        __syncthreads();

        #pragma unroll 2
        for (int kk = 0; kk < 64; ++kk) {
            float4 v0 = *(const float4*)&Vs[kk*132 + tx*8];
            float4 v1 = *(const float4*)&Vs[kk*132 + tx*8 + 4];
            #pragma unroll
            for (int i = 0; i < 4; ++i) {
                const float pp = Ps[(ty*4 + i)*68 + kk];
                oacc[i][0] = fmaf(pp, v0.x, oacc[i][0]);
                oacc[i][1] = fmaf(pp, v0.y, oacc[i][1]);
                oacc[i][2] = fmaf(pp, v0.z, oacc[i][2]);
                oacc[i][3] = fmaf(pp, v0.w, oacc[i][3]);
                oacc[i][4] = fmaf(pp, v1.x, oacc[i][4]);
                oacc[i][5] = fmaf(pp, v1.y, oacc[i][5]);
                oacc[i][6] = fmaf(pp, v1.z, oacc[i][6]);
                oacc[i][7] = fmaf(pp, v1.w, oacc[i][7]);
            }
        }
    }

    #pragma unroll
    for (int i = 0; i < 4; ++i) {
        const float inv = 1.f / l_i[i];
        const int row = q0 + ty*4 + i;
        const size_t idx = headoff + (size_t)row * HID + tx*8;
        __nv_bfloat162* hp = (__nv_bfloat162*)(ohi + idx);
        __nv_bfloat162* lp = (__nv_bfloat162*)(olo + idx);
        #pragma unroll
        for (int c = 0; c < 8; c += 2) {
            float a0 = oacc[i][c]   * inv;
            float a1 = oacc[i][c+1] * inv;
            __nv_bfloat16 h0 = __float2bfloat16(a0);
            __nv_bfloat16 h1 = __float2bfloat16(a1);
            __nv_bfloat16 l0 = __float2bfloat16(a0 - __bfloat162float(h0));
            __nv_bfloat16 l1 = __float2bfloat16(a1 - __bfloat162float(h1));
            hp[c >> 1] = __nv_bfloat162(h0, h1);
            lp[c >> 1] = __nv_bfloat162(l0, l1);
        }
    }
}

// ---------------------------------------------------------------------------
extern "C" void kernel_launch(void* const* d_in, const int* in_sizes, int n_in,
                              void* d_out, int out_size)
{
    (void)in_sizes; (void)n_in; (void)out_size;
    const float* x  = (const float*)d_in[0];
    const float* fr = (const float*)d_in[1];
    const float* w[4] = { (const float*)d_in[2], (const float*)d_in[3],
                          (const float*)d_in[4], (const float*)d_in[5] };
    float* out = (float*)d_out;

    __nv_bfloat16 *xhi, *xlo, *whi, *wlo, *aohi, *aolo;
    float *gq, *gk, *gv;
    cudaGetSymbolAddress((void**)&xhi,  g_x_hi);
    cudaGetSymbolAddress((void**)&xlo,  g_x_lo);
    cudaGetSymbolAddress((void**)&whi,  g_w_hi);
    cudaGetSymbolAddress((void**)&wlo,  g_w_lo);
    cudaGetSymbolAddress((void**)&gq,   g_q);
    cudaGetSymbolAddress((void**)&gk,   g_k);
    cudaGetSymbolAddress((void**)&gv,   g_v);
    cudaGetSymbolAddress((void**)&aohi, g_ao_hi);
    cudaGetSymbolAddress((void**)&aolo, g_ao_lo);

    cudaFuncSetAttribute(gemm_mma, cudaFuncAttributeMaxDynamicSharedMemorySize, GEMM_SMEM);
    cudaFuncSetAttribute(attn_flash, cudaFuncAttributeMaxDynamicSharedMemorySize,
                         ATTN_SMEM_FLOATS * (int)sizeof(float));

    {
        int n4 = (MROWS * HID) / 4;
        split_bf16<<<(n4 + 255) / 256, 256>>>(x, xhi, xlo, n4);
        int w4 = (HID * HID) / 4;
        for (int i = 0; i < 4; ++i)
            split_bf16<<<(w4 + 255) / 256, 256>>>(w[i], whi + (size_t)i * HID * HID,
                                                  wlo + (size_t)i * HID * HID, w4);
    }

    dim3 gg(HID / 128, MROWS / 128);   // (16, 32)
    gemm_mma<<<gg, 256, GEMM_SMEM>>>(xhi, xlo, whi + 0 * (size_t)HID * HID,
                                     wlo + 0 * (size_t)HID * HID, gq, fr, 1);
    gemm_mma<<<gg, 256, GEMM_SMEM>>>(xhi, xlo, whi + 1 * (size_t)HID * HID,
                                     wlo + 1 * (size_t)HID * HID, gk, fr, 1);
    gemm_mma<<<gg, 256, GEMM_SMEM>>>(xhi, xlo, whi + 2 * (size_t)HID * HID,
                                     wlo + 2 * (size_t)HID * HID, gv, nullptr, 0);

    attn_flash<<<dim3(SEQ / 64, BATCH * NHEAD), 256, ATTN_SMEM_FLOATS * (int)sizeof(float)>>>(
        gq, gk, gv, aohi, aolo);

    gemm_mma<<<gg, 256, GEMM_SMEM>>>(aohi, aolo, whi + 3 * (size_t)HID * HID,
                                     wlo + 3 * (size_t)HID * HID, out, nullptr, 0);
}

// round 6
// speedup vs baseline: 1.0296x; 1.0296x over previous
#include <cuda_runtime.h>
#include <cuda_bf16.h>

#define BATCH 2
#define SEQ   2048
#define HID   2048
#define NHEAD 16
#define DK    128
#define MROWS (BATCH*SEQ)

// ---------------- scratch (allocation-free) ----------------
__device__ __nv_bfloat16 g_x_hi[(size_t)MROWS * HID];
__device__ __nv_bfloat16 g_x_lo[(size_t)MROWS * HID];
__device__ __nv_bfloat16 g_w_hi[4][(size_t)HID * HID];
__device__ __nv_bfloat16 g_w_lo[4][(size_t)HID * HID];
__device__ float g_q [(size_t)MROWS * HID];
__device__ float g_k [(size_t)MROWS * HID];
__device__ float g_v [(size_t)MROWS * HID];
__device__ __nv_bfloat16 g_ao_hi[(size_t)MROWS * HID];
__device__ __nv_bfloat16 g_ao_lo[(size_t)MROWS * HID];

// ---------------- PTX helpers (sm_80-era, nothing 'a'-gated) ----------------
__device__ __forceinline__ unsigned smem_u32(const void* p) {
    unsigned a;
    asm("{ .reg .u64 t; cvta.to.shared.u64 t, %1; cvt.u32.u64 %0, t; }" : "=r"(a) : "l"(p));
    return a;
}
__device__ __forceinline__ void cp16(unsigned s, const void* g) {
    asm volatile("cp.async.cg.shared.global [%0], [%1], 16;" :: "r"(s), "l"(g));
}
#define CP_COMMIT() asm volatile("cp.async.commit_group;" ::: "memory")
#define CP_WAIT(n)  asm volatile("cp.async.wait_group %0;" :: "n"(n) : "memory")

__device__ __forceinline__ void ldm4(unsigned* r, unsigned addr) {
    asm volatile("ldmatrix.sync.aligned.m8n8.x4.shared.b16 {%0,%1,%2,%3}, [%4];"
        : "=r"(r[0]), "=r"(r[1]), "=r"(r[2]), "=r"(r[3]) : "r"(addr));
}
__device__ __forceinline__ void mma_bf16(float* d, const unsigned* a, const unsigned* b) {
    asm volatile(
        "mma.sync.aligned.m16n8k16.row.col.f32.bf16.bf16.f32 "
        "{%0,%1,%2,%3}, {%4,%5,%6,%7}, {%8,%9}, {%0,%1,%2,%3};"
        : "+f"(d[0]), "+f"(d[1]), "+f"(d[2]), "+f"(d[3])
        : "r"(a[0]), "r"(a[1]), "r"(a[2]), "r"(a[3]), "r"(b[0]), "r"(b[1]));
}

// ---------------- fp32 -> bf16 hi/lo split ----------------
__global__ __launch_bounds__(256)
void split_bf16(const float* __restrict__ in, __nv_bfloat16* __restrict__ hi,
                __nv_bfloat16* __restrict__ lo, int n4)
{
    int i = blockIdx.x * 256 + threadIdx.x;
    if (i >= n4) return;
    float4 v = ((const float4*)in)[i];
    __nv_bfloat16 h0 = __float2bfloat16(v.x);
    __nv_bfloat16 h1 = __float2bfloat16(v.y);
    __nv_bfloat16 h2 = __float2bfloat16(v.z);
    __nv_bfloat16 h3 = __float2bfloat16(v.w);
    __nv_bfloat16 l0 = __float2bfloat16(v.x - __bfloat162float(h0));
    __nv_bfloat16 l1 = __float2bfloat16(v.y - __bfloat162float(h1));
    __nv_bfloat16 l2 = __float2bfloat16(v.z - __bfloat162float(h2));
    __nv_bfloat16 l3 = __float2bfloat16(v.w - __bfloat162float(h3));
    __nv_bfloat162* hp = (__nv_bfloat162*)hi;
    __nv_bfloat162* lp = (__nv_bfloat162*)lo;
    hp[2*i+0] = __nv_bfloat162(h0, h1);
    hp[2*i+1] = __nv_bfloat162(h2, h3);
    lp[2*i+0] = __nv_bfloat162(l0, l1);
    lp[2*i+1] = __nv_bfloat162(l2, l3);
}

// ---------------- mma.sync GEMM body: C[m][n] = sum_k A[m][k] B[n][k] ----------
// R4-proven config: 128x128 tile, BK=32, 8 warps (2m x 4n), 2-stage cp.async,
// 80KB smem => 2 CTAs/SM (enforced via launch_bounds).
#define BKI 32
#define ROWB 80
#define ARR_BYTES (128 * ROWB)        // 10240
#define OFF_AHI 0
#define OFF_ALO (1 * ARR_BYTES)
#define OFF_BHI (2 * ARR_BYTES)
#define OFF_BLO (3 * ARR_BYTES)
#define STG_BYTES (4 * ARR_BYTES)     // 40960
#define GEMM_SMEM (2 * STG_BYTES)     // 81920
#define NKIT (HID / BKI)              // 64

__device__ __forceinline__ void gemm_load_stage(
    const __nv_bfloat16* __restrict__ Ahi, const __nv_bfloat16* __restrict__ Alo,
    const __nv_bfloat16* __restrict__ Bhi, const __nv_bfloat16* __restrict__ Blo,
    int rowBase, int colBase, int k0, unsigned stage, int t)
{
    const int r    = t >> 1;
    const int half = t & 1;
    const size_t ga = (size_t)(rowBase + r) * HID + k0 + half * 16;
    const size_t gb = (size_t)(colBase + r) * HID + k0 + half * 16;
    const unsigned so = r * ROWB + half * 32;
    cp16(stage + OFF_AHI + so,      Ahi + ga);
    cp16(stage + OFF_AHI + so + 16, Ahi + ga + 8);
    cp16(stage + OFF_ALO + so,      Alo + ga);
    cp16(stage + OFF_ALO + so + 16, Alo + ga + 8);
    cp16(stage + OFF_BHI + so,      Bhi + gb);
    cp16(stage + OFF_BHI + so + 16, Bhi + gb + 8);
    cp16(stage + OFF_BLO + so,      Blo + gb);
    cp16(stage + OFF_BLO + so + 16, Blo + gb + 8);
}

__device__ __forceinline__ void gemm_body(
    const __nv_bfloat16* __restrict__ Ahi, const __nv_bfloat16* __restrict__ Alo,
    const __nv_bfloat16* __restrict__ Bhi, const __nv_bfloat16* __restrict__ Blo,
    float* __restrict__ C, const float* __restrict__ freqs, int do_rope)
{
    extern __shared__ char sm[];
    const unsigned smem = smem_u32(sm);
    const int t    = threadIdx.x;
    const int wid  = t >> 5;
    const int lane = t & 31;
    const int wm   = wid & 1;
    const int wn   = wid >> 1;
    const int rowBase = blockIdx.y * 128;
    const int colBase = blockIdx.x * 128;

    const unsigned aOff = (wm * 64 + (lane & 15)) * ROWB + ((lane >> 4) & 1) * 16;
    const unsigned bOff = (wn * 32 + ((lane >> 4) & 1) * 8 + (lane & 7)) * ROWB
                        + ((lane >> 3) & 1) * 16;

    float acc[4][4][4];
    #pragma unroll
    for (int mt = 0; mt < 4; ++mt)
        #pragma unroll
        for (int nt = 0; nt < 4; ++nt)
            #pragma unroll
            for (int c = 0; c < 4; ++c) acc[mt][nt][c] = 0.f;

    gemm_load_stage(Ahi, Alo, Bhi, Blo, rowBase, colBase, 0, smem, t);
    CP_COMMIT();

    for (int it = 0; it < NKIT; ++it) {
        const unsigned cur = smem + (it & 1) * STG_BYTES;
        if (it + 1 < NKIT) {
            gemm_load_stage(Ahi, Alo, Bhi, Blo, rowBase, colBase, (it + 1) * BKI,
                            smem + ((it + 1) & 1) * STG_BYTES, t);
            CP_COMMIT();
            CP_WAIT(1);
        } else {
            CP_WAIT(0);
        }
        __syncthreads();

        #pragma unroll
        for (int ks = 0; ks < 2; ++ks) {
            const unsigned kofs = ks * 32;
            unsigned ah[4][4], al[4][4], bh[2][4], bl[2][4];
            #pragma unroll
            for (int mt = 0; mt < 4; ++mt) {
                ldm4(ah[mt], cur + OFF_AHI + aOff + mt * (16 * ROWB) + kofs);
                ldm4(al[mt], cur + OFF_ALO + aOff + mt * (16 * ROWB) + kofs);
            }
            #pragma unroll
            for (int p = 0; p < 2; ++p) {
                ldm4(bh[p], cur + OFF_BHI + bOff + p * (16 * ROWB) + kofs);
                ldm4(bl[p], cur + OFF_BLO + bOff + p * (16 * ROWB) + kofs);
            }
            #pragma unroll
            for (int mt = 0; mt < 4; ++mt)
                #pragma unroll
                for (int nt = 0; nt < 4; ++nt) {
                    const unsigned* rbh = &bh[nt >> 1][(nt & 1) * 2];
                    const unsigned* rbl = &bl[nt >> 1][(nt & 1) * 2];
                    mma_bf16(acc[mt][nt], ah[mt], rbh);
                    mma_bf16(acc[mt][nt], ah[mt], rbl);
                    mma_bf16(acc[mt][nt], al[mt], rbh);
                }
        }
        __syncthreads();
    }

    const int g   = lane >> 2;
    const int tig = lane & 3;
    #pragma unroll
    for (int mt = 0; mt < 4; ++mt) {
        #pragma unroll
        for (int nt = 0; nt < 4; ++nt) {
            const int m0 = rowBase + wm * 64 + mt * 16 + g;
            const int n0 = colBase + wn * 32 + nt * 8 + tig * 2;
            float v0 = acc[mt][nt][0], v1 = acc[mt][nt][1];
            float v2 = acc[mt][nt][2], v3 = acc[mt][nt][3];
            if (do_rope) {
                const int d = n0 & (DK - 1);
                const int s0 = m0 & (SEQ - 1);
                const int s1 = (m0 + 8) & (SEQ - 1);
                const float cs0 = freqs[s0 * DK + d], sn0 = freqs[s0 * DK + d + 1];
                const float cs1 = freqs[s1 * DK + d], sn1 = freqs[s1 * DK + d + 1];
                *(float2*)(C + (size_t)m0 * HID + n0) =
                    make_float2(v0 * cs0 - v1 * sn0, v0 * sn0 + v1 * cs0);
                *(float2*)(C + (size_t)(m0 + 8) * HID + n0) =
                    make_float2(v2 * cs1 - v3 * sn1, v2 * sn1 + v3 * cs1);
            } else {
                *(float2*)(C + (size_t)m0 * HID + n0)       = make_float2(v0, v1);
                *(float2*)(C + (size_t)(m0 + 8) * HID + n0) = make_float2(v2, v3);
            }
        }
    }
}

// Fused QKV GEMM: blockIdx.z selects weight / output / rope flag.
__global__ __launch_bounds__(256, 2)
void gemm_qkv(const __nv_bfloat16* __restrict__ xhi, const __nv_bfloat16* __restrict__ xlo,
              const __nv_bfloat16* __restrict__ whi, const __nv_bfloat16* __restrict__ wlo,
              float* __restrict__ q, float* __restrict__ k, float* __restrict__ v,
              const float* __restrict__ freqs)
{
    const int z = blockIdx.z;
    const __nv_bfloat16* bh = whi + (size_t)z * HID * HID;
    const __nv_bfloat16* bl = wlo + (size_t)z * HID * HID;
    float* C = (z == 0) ? q : ((z == 1) ? k : v);
    gemm_body(xhi, xlo, bh, bl, C, freqs, z < 2 ? 1 : 0);
}

__global__ __launch_bounds__(256, 2)
void gemm_single(const __nv_bfloat16* __restrict__ ahi, const __nv_bfloat16* __restrict__ alo,
                 const __nv_bfloat16* __restrict__ bhi, const __nv_bfloat16* __restrict__ blo,
                 float* __restrict__ C)
{
    gemm_body(ahi, alo, bhi, blo, C, nullptr, 0);
}

// ---------------------------------------------------------------------------
// Flash attention, fp32, causal. 64 q-rows x 32-key tiles.
// smem 79,360B => 2 blocks/SM (16 warps) for 2x latency hiding vs R4.
// ---------------------------------------------------------------------------
#define KT 32
#define ATTN_SMEM_BYTES ((128*68 + 128*36 + KT*132 + 64*36) * 4)  // 79,360

__global__ __launch_bounds__(256, 2)
void attn_flash(const float* __restrict__ q, const float* __restrict__ k,
                const float* __restrict__ v,
                __nv_bfloat16* __restrict__ ohi, __nv_bfloat16* __restrict__ olo)
{
    extern __shared__ float smf[];
    float* Qt = smf;                 // [128][68]
    float* Kt = Qt + 128*68;         // [128][36]
    float* Vs = Kt + 128*36;         // [KT][132]
    float* Ps = Vs + KT*132;         // [64][36]

    const int t  = threadIdx.x;
    const int tx = t & 15;
    const int ty = t >> 4;
    const int qt = blockIdx.x;
    const int b  = blockIdx.y >> 4;
    const int h  = blockIdx.y & 15;
    const int q0 = qt * 64;

    const size_t headoff = (size_t)b * SEQ * HID + (size_t)h * DK;
    const float* qb = q + headoff;
    const float* kb = k + headoff;
    const float* vb = v + headoff;

    for (int l = t; l < 64*32; l += 256) {
        const int s  = l >> 5;
        const int d0 = (l & 31) << 2;
        float4 val = *(const float4*)(qb + (size_t)(q0 + s) * HID + d0);
        Qt[(d0+0)*68 + s] = val.x;
        Qt[(d0+1)*68 + s] = val.y;
        Qt[(d0+2)*68 + s] = val.z;
        Qt[(d0+3)*68 + s] = val.w;
    }

    float m_i[4], l_i[4], oacc[4][8];
    #pragma unroll
    for (int i = 0; i < 4; ++i) {
        m_i[i] = -1e30f; l_i[i] = 0.f;
        #pragma unroll
        for (int c = 0; c < 8; ++c) oacc[i][c] = 0.f;
    }
    const float scale = 0.088388347648318447f;  // 1/sqrt(128)

    const int njt = 2 * (qt + 1);   // 32-key tiles covering [0, q0+64)
    for (int j = 0; j < njt; ++j) {
        const int kbase = j * KT;
        __syncthreads();
        // load K (transposed) + V tile: 32 keys x 128 d
        for (int l = t; l < KT*32; l += 256) {
            const int s  = l >> 5;
            const int d0 = (l & 31) << 2;
            float4 kv = *(const float4*)(kb + (size_t)(kbase + s) * HID + d0);
            Kt[(d0+0)*36 + s] = kv.x;
            Kt[(d0+1)*36 + s] = kv.y;
            Kt[(d0+2)*36 + s] = kv.z;
            Kt[(d0+3)*36 + s] = kv.w;
            float4 vv = *(const float4*)(vb + (size_t)(kbase + s) * HID + d0);
            *(float4*)&Vs[s*132 + d0] = vv;
        }
        __syncthreads();

        // S = Q K^T: each thread 4 q-rows (ty*4..) x 4 k-cols (tx*2? -> tx*2)
        // 64 rows x 32 cols over 256 threads: 4x2 per thread
        float sacc[4][2];
        #pragma unroll
        for (int i = 0; i < 4; ++i) { sacc[i][0] = 0.f; sacc[i][1] = 0.f; }

        #pragma unroll 4
        for (int d = 0; d < 128; ++d) {
            float4 qv = *(const float4*)&Qt[d*68 + ty*4];
            float2 kv = *(const float2*)&Kt[d*36 + tx*2];
            float qr[4] = {qv.x, qv.y, qv.z, qv.w};
            #pragma unroll
            for (int i = 0; i < 4; ++i) {
                sacc[i][0] = fmaf(qr[i], kv.x, sacc[i][0]);
                sacc[i][1] = fmaf(qr[i], kv.y, sacc[i][1]);
            }
        }

        #pragma unroll
        for (int i = 0; i < 4; ++i) {
            const int qrow = q0 + ty*4 + i;
            float sv[2];
            #pragma unroll
            for (int jj = 0; jj < 2; ++jj) {
                float x = sacc[i][jj] * scale;
                if (kbase + tx*2 + jj > qrow) x = -1e30f;   // causal
                sv[jj] = x;
            }
            float rm = fmaxf(sv[0], sv[1]);
            #pragma unroll
            for (int off = 8; off > 0; off >>= 1)
                rm = fmaxf(rm, __shfl_xor_sync(0xffffffffu, rm, off, 16));
            const float mnew = fmaxf(m_i[i], rm);
            const float corr = __expf(m_i[i] - mnew);
            float rs = 0.f;
            const int prow = (ty*4 + i)*36 + tx*2;
            #pragma unroll
            for (int jj = 0; jj < 2; ++jj) {
                const float p = __expf(sv[jj] - mnew);
                Ps[prow + jj] = p;
                rs += p;
            }
            #pragma unroll
            for (int off = 8; off > 0; off >>= 1)
                rs += __shfl_xor_sync(0xffffffffu, rs, off, 16);
            l_i[i] = l_i[i] * corr + rs;
            m_i[i] = mnew;
            #pragma unroll
            for (int c = 0; c < 8; ++c) oacc[i][c] *= corr;
        }
        __syncthreads();

        // O += P @ V  (4 rows x 8 cols per thread)
        #pragma unroll 2
        for (int kk = 0; kk < KT; ++kk) {
            float4 v0 = *(const float4*)&Vs[kk*132 + tx*8];
            float4 v1 = *(const float4*)&Vs[kk*132 + tx*8 + 4];
            #pragma unroll
            for (int i = 0; i < 4; ++i) {
                const float pp = Ps[(ty*4 + i)*36 + kk];
                oacc[i][0] = fmaf(pp, v0.x, oacc[i][0]);
                oacc[i][1] = fmaf(pp, v0.y, oacc[i][1]);
                oacc[i][2] = fmaf(pp, v0.z, oacc[i][2]);
                oacc[i][3] = fmaf(pp, v0.w, oacc[i][3]);
                oacc[i][4] = fmaf(pp, v1.x, oacc[i][4]);
                oacc[i][5] = fmaf(pp, v1.y, oacc[i][5]);
                oacc[i][6] = fmaf(pp, v1.z, oacc[i][6]);
                oacc[i][7] = fmaf(pp, v1.w, oacc[i][7]);
            }
        }
    }

    #pragma unroll
    for (int i = 0; i < 4; ++i) {
        const float inv = 1.f / l_i[i];
        const int row = q0 + ty*4 + i;
        const size_t idx = headoff + (size_t)row * HID + tx*8;
        __nv_bfloat162* hp = (__nv_bfloat162*)(ohi + idx);
        __nv_bfloat162* lp = (__nv_bfloat162*)(olo + idx);
        #pragma unroll
        for (int c = 0; c < 8; c += 2) {
            float a0 = oacc[i][c]   * inv;
            float a1 = oacc[i][c+1] * inv;
            __nv_bfloat16 h0 = __float2bfloat16(a0);
            __nv_bfloat16 h1 = __float2bfloat16(a1);
            __nv_bfloat16 l0 = __float2bfloat16(a0 - __bfloat162float(h0));
            __nv_bfloat16 l1 = __float2bfloat16(a1 - __bfloat162float(h1));
            hp[c >> 1] = __nv_bfloat162(h0, h1);
            lp[c >> 1] = __nv_bfloat162(l0, l1);
        }
    }
}

// ---------------------------------------------------------------------------
extern "C" void kernel_launch(void* const* d_in, const int* in_sizes, int n_in,
                              void* d_out, int out_size)
{
    (void)in_sizes; (void)n_in; (void)out_size;
    const float* x  = (const float*)d_in[0];
    const float* fr = (const float*)d_in[1];
    const float* w[4] = { (const float*)d_in[2], (const float*)d_in[3],
                          (const float*)d_in[4], (const float*)d_in[5] };
    float* out = (float*)d_out;

    __nv_bfloat16 *xhi, *xlo, *whi, *wlo, *aohi, *aolo;
    float *gq, *gk, *gv;
    cudaGetSymbolAddress((void**)&xhi,  g_x_hi);
    cudaGetSymbolAddress((void**)&xlo,  g_x_lo);
    cudaGetSymbolAddress((void**)&whi,  g_w_hi);
    cudaGetSymbolAddress((void**)&wlo,  g_w_lo);
    cudaGetSymbolAddress((void**)&gq,   g_q);
    cudaGetSymbolAddress((void**)&gk,   g_k);
    cudaGetSymbolAddress((void**)&gv,   g_v);
    cudaGetSymbolAddress((void**)&aohi, g_ao_hi);
    cudaGetSymbolAddress((void**)&aolo, g_ao_lo);

    cudaFuncSetAttribute(gemm_qkv,    cudaFuncAttributeMaxDynamicSharedMemorySize, GEMM_SMEM);
    cudaFuncSetAttribute(gemm_single, cudaFuncAttributeMaxDynamicSharedMemorySize, GEMM_SMEM);
    cudaFuncSetAttribute(attn_flash,  cudaFuncAttributeMaxDynamicSharedMemorySize, ATTN_SMEM_BYTES);

    // splits first (5 launches) so ncu -s 5 captures gemm_qkv
    {
        int n4 = (MROWS * HID) / 4;
        split_bf16<<<(n4 + 255) / 256, 256>>>(x, xhi, xlo, n4);
        int w4 = (HID * HID) / 4;
        for (int i = 0; i < 4; ++i)
            split_bf16<<<(w4 + 255) / 256, 256>>>(w[i], whi + (size_t)i * HID * HID,
                                                  wlo + (size_t)i * HID * HID, w4);
    }

    dim3 gqkv(HID / 128, MROWS / 128, 3);   // (16, 32, 3) = 1536 CTAs, one launch
    gemm_qkv<<<gqkv, 256, GEMM_SMEM>>>(xhi, xlo, whi, wlo, gq, gk, gv, fr);

    attn_flash<<<dim3(SEQ / 64, BATCH * NHEAD), 256, ATTN_SMEM_BYTES>>>(
        gq, gk, gv, aohi, aolo);

    dim3 gg(HID / 128, MROWS / 128);
    gemm_single<<<gg, 256, GEMM_SMEM>>>(aohi, aolo, whi + 3 * (size_t)HID * HID,
                                        wlo + 3 * (size_t)HID * HID, out);
}

// round 8
// speedup vs baseline: 1.0376x; 1.0078x over previous
#include <cuda_runtime.h>
#include <cuda_bf16.h>

#define BATCH 2
#define SEQ   2048
#define HID   2048
#define NHEAD 16
#define DK    128
#define MROWS (BATCH*SEQ)

// ---------------- scratch (allocation-free) ----------------
__device__ __nv_bfloat16 g_x_hi[(size_t)MROWS * HID];
__device__ __nv_bfloat16 g_x_lo[(size_t)MROWS * HID];
__device__ __nv_bfloat16 g_w_hi[4][(size_t)HID * HID];
__device__ __nv_bfloat16 g_w_lo[4][(size_t)HID * HID];
__device__ float g_q [(size_t)MROWS * HID];
__device__ float g_k [(size_t)MROWS * HID];
__device__ float g_v [(size_t)MROWS * HID];
__device__ __nv_bfloat16 g_ao_hi[(size_t)MROWS * HID];
__device__ __nv_bfloat16 g_ao_lo[(size_t)MROWS * HID];

// ---------------- PTX helpers (sm_80-era, nothing 'a'-gated) ----------------
__device__ __forceinline__ unsigned smem_u32(const void* p) {
    unsigned a;
    asm("{ .reg .u64 t; cvta.to.shared.u64 t, %1; cvt.u32.u64 %0, t; }" : "=r"(a) : "l"(p));
    return a;
}
__device__ __forceinline__ void cp16(unsigned s, const void* g) {
    asm volatile("cp.async.cg.shared.global [%0], [%1], 16;" :: "r"(s), "l"(g));
}
#define CP_COMMIT() asm volatile("cp.async.commit_group;" ::: "memory")
#define CP_WAIT(n)  asm volatile("cp.async.wait_group %0;" :: "n"(n) : "memory")

__device__ __forceinline__ void ldm4(unsigned* r, unsigned addr) {
    asm volatile("ldmatrix.sync.aligned.m8n8.x4.shared.b16 {%0,%1,%2,%3}, [%4];"
        : "=r"(r[0]), "=r"(r[1]), "=r"(r[2]), "=r"(r[3]) : "r"(addr));
}
__device__ __forceinline__ void mma_bf16(float* d, const unsigned* a, const unsigned* b) {
    asm volatile(
        "mma.sync.aligned.m16n8k16.row.col.f32.bf16.bf16.f32 "
        "{%0,%1,%2,%3}, {%4,%5,%6,%7}, {%8,%9}, {%0,%1,%2,%3};"
        : "+f"(d[0]), "+f"(d[1]), "+f"(d[2]), "+f"(d[3])
        : "r"(a[0]), "r"(a[1]), "r"(a[2]), "r"(a[3]), "r"(b[0]), "r"(b[1]));
}

// ---------------- fused fp32 -> bf16 hi/lo split (ONE launch) ----------------
// Regions: x (MROWS*HID), then w0..w3 (HID*HID each). Indexed in float4 units.
#define X4   ((MROWS * HID) / 4)          // 2,097,152
#define W4   ((HID * HID) / 4)            // 1,048,576
#define TOT4 (X4 + 4 * W4)                // 6,291,456

__global__ __launch_bounds__(256)
void split_all(const float* __restrict__ x,
               const float* __restrict__ w0, const float* __restrict__ w1,
               const float* __restrict__ w2, const float* __restrict__ w3,
               __nv_bfloat16* __restrict__ xhi, __nv_bfloat16* __restrict__ xlo,
               __nv_bfloat16* __restrict__ whi, __nv_bfloat16* __restrict__ wlo)
{
    int i = blockIdx.x * 256 + threadIdx.x;
    if (i >= TOT4) return;
    const float* src;
    __nv_bfloat16 *hi, *lo;
    int idx;
    if (i < X4) {
        src = x; hi = xhi; lo = xlo; idx = i;
    } else {
        int j = i - X4;
        int wi = j / W4;
        idx = j - wi * W4;
        const float* ws[4] = {w0, w1, w2, w3};
        src = ws[wi];
        hi = whi + (size_t)wi * HID * HID;
        lo = wlo + (size_t)wi * HID * HID;
    }
    float4 v = ((const float4*)src)[idx];
    __nv_bfloat16 h0 = __float2bfloat16(v.x);
    __nv_bfloat16 h1 = __float2bfloat16(v.y);
    __nv_bfloat16 h2 = __float2bfloat16(v.z);
    __nv_bfloat16 h3 = __float2bfloat16(v.w);
    __nv_bfloat16 l0 = __float2bfloat16(v.x - __bfloat162float(h0));
    __nv_bfloat16 l1 = __float2bfloat16(v.y - __bfloat162float(h1));
    __nv_bfloat16 l2 = __float2bfloat16(v.z - __bfloat162float(h2));
    __nv_bfloat16 l3 = __float2bfloat16(v.w - __bfloat162float(h3));
    __nv_bfloat162* hp = (__nv_bfloat162*)hi;
    __nv_bfloat162* lp = (__nv_bfloat162*)lo;
    hp[2*idx+0] = __nv_bfloat162(h0, h1);
    hp[2*idx+1] = __nv_bfloat162(h2, h3);
    lp[2*idx+0] = __nv_bfloat162(l0, l1);
    lp[2*idx+1] = __nv_bfloat162(l2, l3);
}

// ---------------- mma.sync GEMM body: C[m][n] = sum_k A[m][k] B[n][k] ----------
// R4 config (2-stage, 80KB smem, 2 CTAs/SM) + product-major MMA ordering:
// all 16 hh MMAs, then 16 hl, then 16 lh => same-acc RAW reuses are 16
// independent MMAs apart instead of back-to-back.
#define BKI 32
#define ROWB 80
#define ARR_BYTES (128 * ROWB)        // 10240
#define OFF_AHI 0
#define OFF_ALO (1 * ARR_BYTES)
#define OFF_BHI (2 * ARR_BYTES)
#define OFF_BLO (3 * ARR_BYTES)
#define STG_BYTES (4 * ARR_BYTES)     // 40960
#define GEMM_SMEM (2 * STG_BYTES)     // 81920
#define NKIT (HID / BKI)              // 64

__device__ __forceinline__ void gemm_load_stage(
    const __nv_bfloat16* __restrict__ Ahi, const __nv_bfloat16* __restrict__ Alo,
    const __nv_bfloat16* __restrict__ Bhi, const __nv_bfloat16* __restrict__ Blo,
    int rowBase, int colBase, int k0, unsigned stage, int t)
{
    const int r    = t >> 1;
    const int half = t & 1;
    const size_t ga = (size_t)(rowBase + r) * HID + k0 + half * 16;
    const size_t gb = (size_t)(colBase + r) * HID + k0 + half * 16;
    const unsigned so = r * ROWB + half * 32;
    cp16(stage + OFF_AHI + so,      Ahi + ga);
    cp16(stage + OFF_AHI + so + 16, Ahi + ga + 8);
    cp16(stage + OFF_ALO + so,      Alo + ga);
    cp16(stage + OFF_ALO + so + 16, Alo + ga + 8);
    cp16(stage + OFF_BHI + so,      Bhi + gb);
    cp16(stage + OFF_BHI + so + 16, Bhi + gb + 8);
    cp16(stage + OFF_BLO + so,      Blo + gb);
    cp16(stage + OFF_BLO + so + 16, Blo + gb + 8);
}

__device__ __forceinline__ void gemm_body(
    const __nv_bfloat16* __restrict__ Ahi, const __nv_bfloat16* __restrict__ Alo,
    const __nv_bfloat16* __restrict__ Bhi, const __nv_bfloat16* __restrict__ Blo,
    float* __restrict__ C, const float* __restrict__ freqs, int do_rope)
{
    extern __shared__ char sm[];
    const unsigned smem = smem_u32(sm);
    const int t    = threadIdx.x;
    const int wid  = t >> 5;
    const int lane = t & 31;
    const int wm   = wid & 1;
    const int wn   = wid >> 1;
    const int rowBase = blockIdx.y * 128;
    const int colBase = blockIdx.x * 128;

    const unsigned aOff = (wm * 64 + (lane & 15)) * ROWB + ((lane >> 4) & 1) * 16;
    const unsigned bOff = (wn * 32 + ((lane >> 4) & 1) * 8 + (lane & 7)) * ROWB
                        + ((lane >> 3) & 1) * 16;

    float acc[4][4][4];
    #pragma unroll
    for (int mt = 0; mt < 4; ++mt)
        #pragma unroll
        for (int nt = 0; nt < 4; ++nt)
            #pragma unroll
            for (int c = 0; c < 4; ++c) acc[mt][nt][c] = 0.f;

    gemm_load_stage(Ahi, Alo, Bhi, Blo, rowBase, colBase, 0, smem, t);
    CP_COMMIT();

    for (int it = 0; it < NKIT; ++it) {
        const unsigned cur = smem + (it & 1) * STG_BYTES;
        if (it + 1 < NKIT) {
            gemm_load_stage(Ahi, Alo, Bhi, Blo, rowBase, colBase, (it + 1) * BKI,
                            smem + ((it + 1) & 1) * STG_BYTES, t);
            CP_COMMIT();
            CP_WAIT(1);
        } else {
            CP_WAIT(0);
        }
        __syncthreads();

        #pragma unroll
        for (int ks = 0; ks < 2; ++ks) {
            const unsigned kofs = ks * 32;
            unsigned ah[4][4], al[4][4], bh[2][4], bl[2][4];
            #pragma unroll
            for (int mt = 0; mt < 4; ++mt) {
                ldm4(ah[mt], cur + OFF_AHI + aOff + mt * (16 * ROWB) + kofs);
                ldm4(al[mt], cur + OFF_ALO + aOff + mt * (16 * ROWB) + kofs);
            }
            #pragma unroll
            for (int p = 0; p < 2; ++p) {
                ldm4(bh[p], cur + OFF_BHI + bOff + p * (16 * ROWB) + kofs);
                ldm4(bl[p], cur + OFF_BLO + bOff + p * (16 * ROWB) + kofs);
            }
            // product-major: same-acc reuses separated by 16 independent MMAs
            #pragma unroll
            for (int mt = 0; mt < 4; ++mt)
                #pragma unroll
                for (int nt = 0; nt < 4; ++nt)
                    mma_bf16(acc[mt][nt], ah[mt], &bh[nt >> 1][(nt & 1) * 2]);
            #pragma unroll
            for (int mt = 0; mt < 4; ++mt)
                #pragma unroll
                for (int nt = 0; nt < 4; ++nt)
                    mma_bf16(acc[mt][nt], ah[mt], &bl[nt >> 1][(nt & 1) * 2]);
            #pragma unroll
            for (int mt = 0; mt < 4; ++mt)
                #pragma unroll
                for (int nt = 0; nt < 4; ++nt)
                    mma_bf16(acc[mt][nt], al[mt], &bh[nt >> 1][(nt & 1) * 2]);
        }
        __syncthreads();
    }

    const int g   = lane >> 2;
    const int tig = lane & 3;
    #pragma unroll
    for (int mt = 0; mt < 4; ++mt) {
        #pragma unroll
        for (int nt = 0; nt < 4; ++nt) {
            const int m0 = rowBase + wm * 64 + mt * 16 + g;
            const int n0 = colBase + wn * 32 + nt * 8 + tig * 2;
            float v0 = acc[mt][nt][0], v1 = acc[mt][nt][1];
            float v2 = acc[mt][nt][2], v3 = acc[mt][nt][3];
            if (do_rope) {
                const int d = n0 & (DK - 1);
                const int s0 = m0 & (SEQ - 1);
                const int s1 = (m0 + 8) & (SEQ - 1);
                const float cs0 = freqs[s0 * DK + d], sn0 = freqs[s0 * DK + d + 1];
                const float cs1 = freqs[s1 * DK + d], sn1 = freqs[s1 * DK + d + 1];
                *(float2*)(C + (size_t)m0 * HID + n0) =
                    make_float2(v0 * cs0 - v1 * sn0, v0 * sn0 + v1 * cs0);
                *(float2*)(C + (size_t)(m0 + 8) * HID + n0) =
                    make_float2(v2 * cs1 - v3 * sn1, v2 * sn1 + v3 * cs1);
            } else {
                *(float2*)(C + (size_t)m0 * HID + n0)       = make_float2(v0, v1);
                *(float2*)(C + (size_t)(m0 + 8) * HID + n0) = make_float2(v2, v3);
            }
        }
    }
}

// Fused QKV GEMM: blockIdx.z selects weight / output / rope flag.
__global__ __launch_bounds__(256, 2)
void gemm_qkv(const __nv_bfloat16* __restrict__ xhi, const __nv_bfloat16* __restrict__ xlo,
              const __nv_bfloat16* __restrict__ whi, const __nv_bfloat16* __restrict__ wlo,
              float* __restrict__ q, float* __restrict__ k, float* __restrict__ v,
              const float* __restrict__ freqs)
{
    const int z = blockIdx.z;
    const __nv_bfloat16* bh = whi + (size_t)z * HID * HID;
    const __nv_bfloat16* bl = wlo + (size_t)z * HID * HID;
    float* C = (z == 0) ? q : ((z == 1) ? k : v);
    gemm_body(xhi, xlo, bh, bl, C, freqs, z < 2 ? 1 : 0);
}

__global__ __launch_bounds__(256, 2)
void gemm_single(const __nv_bfloat16* __restrict__ ahi, const __nv_bfloat16* __restrict__ alo,
                 const __nv_bfloat16* __restrict__ bhi, const __nv_bfloat16* __restrict__ blo,
                 float* __restrict__ C)
{
    gemm_body(ahi, alo, bhi, blo, C, nullptr, 0);
}

// ---------------------------------------------------------------------------
// Flash attention, fp32, causal. 64 q-rows x 32-key tiles, 2 blocks/SM.
// ---------------------------------------------------------------------------
#define KT 32
#define ATTN_SMEM_BYTES ((128*68 + 128*36 + KT*132 + 64*36) * 4)  // 79,360

__global__ __launch_bounds__(256, 2)
void attn_flash(const float* __restrict__ q, const float* __restrict__ k,
                const float* __restrict__ v,
                __nv_bfloat16* __restrict__ ohi, __nv_bfloat16* __restrict__ olo)
{
    extern __shared__ float smf[];
    float* Qt = smf;                 // [128][68]
    float* Kt = Qt + 128*68;         // [128][36]
    float* Vs = Kt + 128*36;         // [KT][132]
    float* Ps = Vs + KT*132;         // [64][36]

    const int t  = threadIdx.x;
    const int tx = t & 15;
    const int ty = t >> 4;
    const int qt = blockIdx.x;
    const int b  = blockIdx.y >> 4;
    const int h  = blockIdx.y & 15;
    const int q0 = qt * 64;

    const size_t headoff = (size_t)b * SEQ * HID + (size_t)h * DK;
    const float* qb = q + headoff;
    const float* kb = k + headoff;
    const float* vb = v + headoff;

    for (int l = t; l < 64*32; l += 256) {
        const int s  = l >> 5;
        const int d0 = (l & 31) << 2;
        float4 val = *(const float4*)(qb + (size_t)(q0 + s) * HID + d0);
        Qt[(d0+0)*68 + s] = val.x;
        Qt[(d0+1)*68 + s] = val.y;
        Qt[(d0+2)*68 + s] = val.z;
        Qt[(d0+3)*68 + s] = val.w;
    }

    float m_i[4], l_i[4], oacc[4][8];
    #pragma unroll
    for (int i = 0; i < 4; ++i) {
        m_i[i] = -1e30f; l_i[i] = 0.f;
        #pragma unroll
        for (int c = 0; c < 8; ++c) oacc[i][c] = 0.f;
    }
    const float scale = 0.088388347648318447f;  // 1/sqrt(128)

    const int njt = 2 * (qt + 1);
    for (int j = 0; j < njt; ++j) {
        const int kbase = j * KT;
        __syncthreads();
        for (int l = t; l < KT*32; l += 256) {
            const int s  = l >> 5;
            const int d0 = (l & 31) << 2;
            float4 kv = *(const float4*)(kb + (size_t)(kbase + s) * HID + d0);
            Kt[(d0+0)*36 + s] = kv.x;
            Kt[(d0+1)*36 + s] = kv.y;
            Kt[(d0+2)*36 + s] = kv.z;
            Kt[(d0+3)*36 + s] = kv.w;
            float4 vv = *(const float4*)(vb + (size_t)(kbase + s) * HID + d0);
            *(float4*)&Vs[s*132 + d0] = vv;
        }
        __syncthreads();

        float sacc[4][2];
        #pragma unroll
        for (int i = 0; i < 4; ++i) { sacc[i][0] = 0.f; sacc[i][1] = 0.f; }

        #pragma unroll 4
        for (int d = 0; d < 128; ++d) {
            float4 qv = *(const float4*)&Qt[d*68 + ty*4];
            float2 kv = *(const float2*)&Kt[d*36 + tx*2];
            float qr[4] = {qv.x, qv.y, qv.z, qv.w};
            #pragma unroll
            for (int i = 0; i < 4; ++i) {
                sacc[i][0] = fmaf(qr[i], kv.x, sacc[i][0]);
                sacc[i][1] = fmaf(qr[i], kv.y, sacc[i][1]);
            }
        }

        #pragma unroll
        for (int i = 0; i < 4; ++i) {
            const int qrow = q0 + ty*4 + i;
            float sv[2];
            #pragma unroll
            for (int jj = 0; jj < 2; ++jj) {
                float x = sacc[i][jj] * scale;
                if (kbase + tx*2 + jj > qrow) x = -1e30f;
                sv[jj] = x;
            }
            float rm = fmaxf(sv[0], sv[1]);
            #pragma unroll
            for (int off = 8; off > 0; off >>= 1)
                rm = fmaxf(rm, __shfl_xor_sync(0xffffffffu, rm, off, 16));
            const float mnew = fmaxf(m_i[i], rm);
            const float corr = __expf(m_i[i] - mnew);
            float rs = 0.f;
            const int prow = (ty*4 + i)*36 + tx*2;
            #pragma unroll
            for (int jj = 0; jj < 2; ++jj) {
                const float p = __expf(sv[jj] - mnew);
                Ps[prow + jj] = p;
                rs += p;
            }
            #pragma unroll
            for (int off = 8; off > 0; off >>= 1)
                rs += __shfl_xor_sync(0xffffffffu, rs, off, 16);
            l_i[i] = l_i[i] * corr + rs;
            m_i[i] = mnew;
            #pragma unroll
            for (int c = 0; c < 8; ++c) oacc[i][c] *= corr;
        }
        __syncthreads();

        #pragma unroll 2
        for (int kk = 0; kk < KT; ++kk) {
            float4 v0 = *(const float4*)&Vs[kk*132 + tx*8];
            float4 v1 = *(const float4*)&Vs[kk*132 + tx*8 + 4];
            #pragma unroll
            for (int i = 0; i < 4; ++i) {
                const float pp = Ps[(ty*4 + i)*36 + kk];
                oacc[i][0] = fmaf(pp, v0.x, oacc[i][0]);
                oacc[i][1] = fmaf(pp, v0.y, oacc[i][1]);
                oacc[i][2] = fmaf(pp, v0.z, oacc[i][2]);
                oacc[i][3] = fmaf(pp, v0.w, oacc[i][3]);
                oacc[i][4] = fmaf(pp, v1.x, oacc[i][4]);
                oacc[i][5] = fmaf(pp, v1.y, oacc[i][5]);
                oacc[i][6] = fmaf(pp, v1.z, oacc[i][6]);
                oacc[i][7] = fmaf(pp, v1.w, oacc[i][7]);
            }
        }
    }

    #pragma unroll
    for (int i = 0; i < 4; ++i) {
        const float inv = 1.f / l_i[i];
        const int row = q0 + ty*4 + i;
        const size_t idx = headoff + (size_t)row * HID + tx*8;
        __nv_bfloat162* hp = (__nv_bfloat162*)(ohi + idx);
        __nv_bfloat162* lp = (__nv_bfloat162*)(olo + idx);
        #pragma unroll
        for (int c = 0; c < 8; c += 2) {
            float a0 = oacc[i][c]   * inv;
            float a1 = oacc[i][c+1] * inv;
            __nv_bfloat16 h0 = __float2bfloat16(a0);
            __nv_bfloat16 h1 = __float2bfloat16(a1);
            __nv_bfloat16 l0 = __float2bfloat16(a0 - __bfloat162float(h0));
            __nv_bfloat16 l1 = __float2bfloat16(a1 - __bfloat162float(h1));
            hp[c >> 1] = __nv_bfloat162(h0, h1);
            lp[c >> 1] = __nv_bfloat162(l0, l1);
        }
    }
}

// ---------------------------------------------------------------------------
extern "C" void kernel_launch(void* const* d_in, const int* in_sizes, int n_in,
                              void* d_out, int out_size)
{
    (void)in_sizes; (void)n_in; (void)out_size;
    const float* x  = (const float*)d_in[0];
    const float* fr = (const float*)d_in[1];
    const float* w0 = (const float*)d_in[2];
    const float* w1 = (const float*)d_in[3];
    const float* w2 = (const float*)d_in[4];
    const float* w3 = (const float*)d_in[5];
    float* out = (float*)d_out;

    __nv_bfloat16 *xhi, *xlo, *whi, *wlo, *aohi, *aolo;
    float *gq, *gk, *gv;
    cudaGetSymbolAddress((void**)&xhi,  g_x_hi);
    cudaGetSymbolAddress((void**)&xlo,  g_x_lo);
    cudaGetSymbolAddress((void**)&whi,  g_w_hi);
    cudaGetSymbolAddress((void**)&wlo,  g_w_lo);
    cudaGetSymbolAddress((void**)&gq,   g_q);
    cudaGetSymbolAddress((void**)&gk,   g_k);
    cudaGetSymbolAddress((void**)&gv,   g_v);
    cudaGetSymbolAddress((void**)&aohi, g_ao_hi);
    cudaGetSymbolAddress((void**)&aolo, g_ao_lo);

    cudaFuncSetAttribute(gemm_qkv,    cudaFuncAttributeMaxDynamicSharedMemorySize, GEMM_SMEM);
    cudaFuncSetAttribute(gemm_single, cudaFuncAttributeMaxDynamicSharedMemorySize, GEMM_SMEM);
    cudaFuncSetAttribute(attn_flash,  cudaFuncAttributeMaxDynamicSharedMemorySize, ATTN_SMEM_BYTES);

    // ONE split launch (4 launches/replay total: ncu -s 5 lands on gemm_qkv)
    split_all<<<(TOT4 + 255) / 256, 256>>>(x, w0, w1, w2, w3, xhi, xlo, whi, wlo);

    dim3 gqkv(HID / 128, MROWS / 128, 3);
    gemm_qkv<<<gqkv, 256, GEMM_SMEM>>>(xhi, xlo, whi, wlo, gq, gk, gv, fr);

    attn_flash<<<dim3(SEQ / 64, BATCH * NHEAD), 256, ATTN_SMEM_BYTES>>>(
        gq, gk, gv, aohi, aolo);

    dim3 gg(HID / 128, MROWS / 128);
    gemm_single<<<gg, 256, GEMM_SMEM>>>(aohi, aolo, whi + 3 * (size_t)HID * HID,
                                        wlo + 3 * (size_t)HID * HID, out);
}

// round 10
// speedup vs baseline: 1.4994x; 1.4451x over previous
#include <cuda_runtime.h>
#include <cuda_bf16.h>

#define BATCH 2
#define SEQ   2048
#define HID   2048
#define NHEAD 16
#define DK    128
#define MROWS (BATCH*SEQ)

// ---------------- scratch (allocation-free) ----------------
__device__ __nv_bfloat16 g_x_hi[(size_t)MROWS * HID];
__device__ __nv_bfloat16 g_x_lo[(size_t)MROWS * HID];
__device__ __nv_bfloat16 g_w_hi[4][(size_t)HID * HID];
__device__ __nv_bfloat16 g_w_lo[4][(size_t)HID * HID];
__device__ __nv_bfloat16 g_q_hi[(size_t)MROWS * HID];
__device__ __nv_bfloat16 g_q_lo[(size_t)MROWS * HID];
__device__ __nv_bfloat16 g_k_hi[(size_t)MROWS * HID];
__device__ __nv_bfloat16 g_k_lo[(size_t)MROWS * HID];
__device__ __nv_bfloat16 g_v_hi[(size_t)MROWS * HID];
__device__ __nv_bfloat16 g_v_lo[(size_t)MROWS * HID];
__device__ __nv_bfloat16 g_ao_hi[(size_t)MROWS * HID];
__device__ __nv_bfloat16 g_ao_lo[(size_t)MROWS * HID];

// ---------------- PTX helpers (sm_80-era, nothing 'a'-gated) ----------------
__device__ __forceinline__ unsigned smem_u32(const void* p) {
    unsigned a;
    asm("{ .reg .u64 t; cvta.to.shared.u64 t, %1; cvt.u32.u64 %0, t; }" : "=r"(a) : "l"(p));
    return a;
}
__device__ __forceinline__ void cp16(unsigned s, const void* g) {
    asm volatile("cp.async.cg.shared.global [%0], [%1], 16;" :: "r"(s), "l"(g));
}
#define CP_COMMIT() asm volatile("cp.async.commit_group;" ::: "memory")
#define CP_WAIT(n)  asm volatile("cp.async.wait_group %0;" :: "n"(n) : "memory")

__device__ __forceinline__ void ldm4(unsigned* r, unsigned addr) {
    asm volatile("ldmatrix.sync.aligned.m8n8.x4.shared.b16 {%0,%1,%2,%3}, [%4];"
        : "=r"(r[0]), "=r"(r[1]), "=r"(r[2]), "=r"(r[3]) : "r"(addr));
}
__device__ __forceinline__ void mma_bf16(float* d, const unsigned* a, const unsigned* b) {
    asm volatile(
        "mma.sync.aligned.m16n8k16.row.col.f32.bf16.bf16.f32 "
        "{%0,%1,%2,%3}, {%4,%5,%6,%7}, {%8,%9}, {%0,%1,%2,%3};"
        : "+f"(d[0]), "+f"(d[1]), "+f"(d[2]), "+f"(d[3])
        : "r"(a[0]), "r"(a[1]), "r"(a[2]), "r"(a[3]), "r"(b[0]), "r"(b[1]));
}

__device__ __forceinline__ __nv_bfloat162 split_pair(float a0, float a1,
                                                     __nv_bfloat162* lo_out) {
    __nv_bfloat16 h0 = __float2bfloat16(a0);
    __nv_bfloat16 h1 = __float2bfloat16(a1);
    *lo_out = __nv_bfloat162(__float2bfloat16(a0 - __bfloat162float(h0)),
                             __float2bfloat16(a1 - __bfloat162float(h1)));
    return __nv_bfloat162(h0, h1);
}

// ---------------- fused fp32 -> bf16 hi/lo split (ONE launch) ----------------
#define X4   ((MROWS * HID) / 4)
#define W4   ((HID * HID) / 4)
#define TOT4 (X4 + 4 * W4)

__global__ __launch_bounds__(256)
void split_all(const float* __restrict__ x,
               const float* __restrict__ w0, const float* __restrict__ w1,
               const float* __restrict__ w2, const float* __restrict__ w3,
               __nv_bfloat16* __restrict__ xhi, __nv_bfloat16* __restrict__ xlo,
               __nv_bfloat16* __restrict__ whi, __nv_bfloat16* __restrict__ wlo)
{
    int i = blockIdx.x * 256 + threadIdx.x;
    if (i >= TOT4) return;
    const float* src;
    __nv_bfloat16 *hi, *lo;
    int idx;
    if (i < X4) {
        src = x; hi = xhi; lo = xlo; idx = i;
    } else {
        int j = i - X4;
        int wi = j / W4;
        idx = j - wi * W4;
        const float* ws[4] = {w0, w1, w2, w3};
        src = ws[wi];
        hi = whi + (size_t)wi * HID * HID;
        lo = wlo + (size_t)wi * HID * HID;
    }
    float4 v = ((const float4*)src)[idx];
    __nv_bfloat162 l0, l1;
    __nv_bfloat162 h0 = split_pair(v.x, v.y, &l0);
    __nv_bfloat162 h1 = split_pair(v.z, v.w, &l1);
    ((__nv_bfloat162*)hi)[2*idx+0] = h0;
    ((__nv_bfloat162*)hi)[2*idx+1] = h1;
    ((__nv_bfloat162*)lo)[2*idx+0] = l0;
    ((__nv_bfloat162*)lo)[2*idx+1] = l1;
}

// ---------------- mma.sync GEMM body ----------------
#define BKI 32
#define ROWB 80
#define ARR_BYTES (128 * ROWB)
#define OFF_AHI 0
#define OFF_ALO (1 * ARR_BYTES)
#define OFF_BHI (2 * ARR_BYTES)
#define OFF_BLO (3 * ARR_BYTES)
#define STG_BYTES (4 * ARR_BYTES)
#define GEMM_SMEM (2 * STG_BYTES)
#define NKIT (HID / BKI)

__device__ __forceinline__ void gemm_load_stage(
    const __nv_bfloat16* __restrict__ Ahi, const __nv_bfloat16* __restrict__ Alo,
    const __nv_bfloat16* __restrict__ Bhi, const __nv_bfloat16* __restrict__ Blo,
    int rowBase, int colBase, int k0, unsigned stage, int t)
{
    const int r    = t >> 1;
    const int half = t & 1;
    const size_t ga = (size_t)(rowBase + r) * HID + k0 + half * 16;
    const size_t gb = (size_t)(colBase + r) * HID + k0 + half * 16;
    const unsigned so = r * ROWB + half * 32;
    cp16(stage + OFF_AHI + so,      Ahi + ga);
    cp16(stage + OFF_AHI + so + 16, Ahi + ga + 8);
    cp16(stage + OFF_ALO + so,      Alo + ga);
    cp16(stage + OFF_ALO + so + 16, Alo + ga + 8);
    cp16(stage + OFF_BHI + so,      Bhi + gb);
    cp16(stage + OFF_BHI + so + 16, Bhi + gb + 8);
    cp16(stage + OFF_BLO + so,      Blo + gb);
    cp16(stage + OFF_BLO + so + 16, Blo + gb + 8);
}

// If Cf != nullptr: write fp32. Else write bf16 hi/lo split to Chi/Clo.
__device__ __forceinline__ void gemm_body(
    const __nv_bfloat16* __restrict__ Ahi, const __nv_bfloat16* __restrict__ Alo,
    const __nv_bfloat16* __restrict__ Bhi, const __nv_bfloat16* __restrict__ Blo,
    float* __restrict__ Cf,
    __nv_bfloat16* __restrict__ Chi, __nv_bfloat16* __restrict__ Clo,
    const float* __restrict__ freqs, int do_rope)
{
    extern __shared__ char sm[];
    const unsigned smem = smem_u32(sm);
    const int t    = threadIdx.x;
    const int wid  = t >> 5;
    const int lane = t & 31;
    const int wm   = wid & 1;
    const int wn   = wid >> 1;
    const int rowBase = blockIdx.y * 128;
    const int colBase = blockIdx.x * 128;

    const unsigned aOff = (wm * 64 + (lane & 15)) * ROWB + ((lane >> 4) & 1) * 16;
    const unsigned bOff = (wn * 32 + ((lane >> 4) & 1) * 8 + (lane & 7)) * ROWB
                        + ((lane >> 3) & 1) * 16;

    float acc[4][4][4];
    #pragma unroll
    for (int mt = 0; mt < 4; ++mt)
        #pragma unroll
        for (int nt = 0; nt < 4; ++nt)
            #pragma unroll
            for (int c = 0; c < 4; ++c) acc[mt][nt][c] = 0.f;

    gemm_load_stage(Ahi, Alo, Bhi, Blo, rowBase, colBase, 0, smem, t);
    CP_COMMIT();

    for (int it = 0; it < NKIT; ++it) {
        const unsigned cur = smem + (it & 1) * STG_BYTES;
        if (it + 1 < NKIT) {
            gemm_load_stage(Ahi, Alo, Bhi, Blo, rowBase, colBase, (it + 1) * BKI,
                            smem + ((it + 1) & 1) * STG_BYTES, t);
            CP_COMMIT();
            CP_WAIT(1);
        } else {
            CP_WAIT(0);
        }
        __syncthreads();

        #pragma unroll
        for (int ks = 0; ks < 2; ++ks) {
            const unsigned kofs = ks * 32;
            unsigned ah[4][4], al[4][4], bh[2][4], bl[2][4];
            #pragma unroll
            for (int mt = 0; mt < 4; ++mt) {
                ldm4(ah[mt], cur + OFF_AHI + aOff + mt * (16 * ROWB) + kofs);
                ldm4(al[mt], cur + OFF_ALO + aOff + mt * (16 * ROWB) + kofs);
            }
            #pragma unroll
            for (int p = 0; p < 2; ++p) {
                ldm4(bh[p], cur + OFF_BHI + bOff + p * (16 * ROWB) + kofs);
                ldm4(bl[p], cur + OFF_BLO + bOff + p * (16 * ROWB) + kofs);
            }
            #pragma unroll
            for (int mt = 0; mt < 4; ++mt)
                #pragma unroll
                for (int nt = 0; nt < 4; ++nt)
                    mma_bf16(acc[mt][nt], ah[mt], &bh[nt >> 1][(nt & 1) * 2]);
            #pragma unroll
            for (int mt = 0; mt < 4; ++mt)
                #pragma unroll
                for (int nt = 0; nt < 4; ++nt)
                    mma_bf16(acc[mt][nt], ah[mt], &bl[nt >> 1][(nt & 1) * 2]);
            #pragma unroll
            for (int mt = 0; mt < 4; ++mt)
                #pragma unroll
                for (int nt = 0; nt < 4; ++nt)
                    mma_bf16(acc[mt][nt], al[mt], &bh[nt >> 1][(nt & 1) * 2]);
        }
        __syncthreads();
    }

    const int g   = lane >> 2;
    const int tig = lane & 3;
    #pragma unroll
    for (int mt = 0; mt < 4; ++mt) {
        #pragma unroll
        for (int nt = 0; nt < 4; ++nt) {
            const int m0 = rowBase + wm * 64 + mt * 16 + g;
            const int n0 = colBase + wn * 32 + nt * 8 + tig * 2;
            float v0 = acc[mt][nt][0], v1 = acc[mt][nt][1];
            float v2 = acc[mt][nt][2], v3 = acc[mt][nt][3];
            if (do_rope) {
                const int d = n0 & (DK - 1);
                const int s0 = m0 & (SEQ - 1);
                const int s1 = (m0 + 8) & (SEQ - 1);
                const float cs0 = freqs[s0 * DK + d], sn0 = freqs[s0 * DK + d + 1];
                const float cs1 = freqs[s1 * DK + d], sn1 = freqs[s1 * DK + d + 1];
                float r0 = v0 * cs0 - v1 * sn0, r1 = v0 * sn0 + v1 * cs0;
                float r2 = v2 * cs1 - v3 * sn1, r3 = v2 * sn1 + v3 * cs1;
                v0 = r0; v1 = r1; v2 = r2; v3 = r3;
            }
            if (Cf) {
                *(float2*)(Cf + (size_t)m0 * HID + n0)       = make_float2(v0, v1);
                *(float2*)(Cf + (size_t)(m0 + 8) * HID + n0) = make_float2(v2, v3);
            } else {
                __nv_bfloat162 l0, l1;
                __nv_bfloat162 h0 = split_pair(v0, v1, &l0);
                __nv_bfloat162 h1 = split_pair(v2, v3, &l1);
                *(__nv_bfloat162*)(Chi + (size_t)m0 * HID + n0)       = h0;
                *(__nv_bfloat162*)(Chi + (size_t)(m0 + 8) * HID + n0) = h1;
                *(__nv_bfloat162*)(Clo + (size_t)m0 * HID + n0)       = l0;
                *(__nv_bfloat162*)(Clo + (size_t)(m0 + 8) * HID + n0) = l1;
            }
        }
    }
}

__global__ __launch_bounds__(256, 2)
void gemm_qkv(const __nv_bfloat16* __restrict__ xhi, const __nv_bfloat16* __restrict__ xlo,
              const __nv_bfloat16* __restrict__ whi, const __nv_bfloat16* __restrict__ wlo,
              __nv_bfloat16* __restrict__ qhi, __nv_bfloat16* __restrict__ qlo,
              __nv_bfloat16* __restrict__ khi, __nv_bfloat16* __restrict__ klo,
              __nv_bfloat16* __restrict__ vhi, __nv_bfloat16* __restrict__ vlo,
              const float* __restrict__ freqs)
{
    const int z = blockIdx.z;
    const __nv_bfloat16* bh = whi + (size_t)z * HID * HID;
    const __nv_bfloat16* bl = wlo + (size_t)z * HID * HID;
    __nv_bfloat16* Chi = (z == 0) ? qhi : ((z == 1) ? khi : vhi);
    __nv_bfloat16* Clo = (z == 0) ? qlo : ((z == 1) ? klo : vlo);
    gemm_body(xhi, xlo, bh, bl, nullptr, Chi, Clo, freqs, z < 2 ? 1 : 0);
}

__global__ __launch_bounds__(256, 2)
void gemm_single(const __nv_bfloat16* __restrict__ ahi, const __nv_bfloat16* __restrict__ alo,
                 const __nv_bfloat16* __restrict__ bhi, const __nv_bfloat16* __restrict__ blo,
                 float* __restrict__ C)
{
    gemm_body(ahi, alo, bhi, blo, C, nullptr, nullptr, nullptr, 0);
}

// ---------------------------------------------------------------------------
// Tensorized flash attention (bf16 hi/lo, 3-product), fp32 softmax/O state.
// Block: 64 q-rows x one head. 8 warps: wm=wid&3 (16-row groups),
// wn=wid>>2 (key/column halves). KT=32 keys per tile.
// smem pitches: 272B for 128-dim rows (Q,K), 80B for 32-key rows (Vt,P).
// ---------------------------------------------------------------------------
#define KT2    32
#define QP     272            // 128 dims * 2B + 16 pad
#define PP     80             // 32 keys * 2B + 16 pad
#define SQ_HI  0
#define SQ_LO  (SQ_HI + 64 * QP)       // 17408
#define SK_HI  (SQ_LO + 64 * QP)       // 34816
#define SK_LO  (SK_HI + 32 * QP)       // 43520
#define SVT_HI (SK_LO + 32 * QP)       // 52224
#define SVT_LO (SVT_HI + 128 * PP)     // 62464
#define SP_HI  (SVT_LO + 128 * PP)     // 72704
#define SP_LO  (SP_HI + 64 * PP)       // 77824
#define RED_MX (SP_LO + 64 * PP)       // 82944
#define RED_SM (RED_MX + 2 * 64 * 4)   // 83456
#define ATTN_SMEM (RED_SM + 2 * 64 * 4) // 83968

__global__ __launch_bounds__(256, 2)
void attn_mma(const __nv_bfloat16* __restrict__ qhi, const __nv_bfloat16* __restrict__ qlo,
              const __nv_bfloat16* __restrict__ khi, const __nv_bfloat16* __restrict__ klo,
              const __nv_bfloat16* __restrict__ vhi, const __nv_bfloat16* __restrict__ vlo,
              __nv_bfloat16* __restrict__ ohi, __nv_bfloat16* __restrict__ olo)
{
    extern __shared__ char sm[];
    const unsigned smem = smem_u32(sm);
    float* redmx = (float*)(sm + RED_MX);
    float* redsm = (float*)(sm + RED_SM);

    const int t    = threadIdx.x;
    const int wid  = t >> 5;
    const int lane = t & 31;
    const int wm   = wid & 3;           // 16-row group
    const int wn   = wid >> 2;          // 0/1
    const int g    = lane >> 2;
    const int tig  = lane & 3;

    const int qt = gridDim.x - 1 - blockIdx.x;   // longest tiles first
    const int b  = blockIdx.y >> 4;
    const int h  = blockIdx.y & 15;
    const int q0 = qt * 64;
    const size_t headoff = (size_t)b * SEQ * HID + (size_t)h * DK;

    // fragment base offsets
    const unsigned aQ = (wm * 16 + (lane & 15)) * QP + ((lane >> 4) & 1) * 16;
    const unsigned bK = (wn * 16 + ((lane >> 4) & 1) * 8 + (lane & 7)) * QP
                      + ((lane >> 3) & 1) * 16;
    const unsigned aP = (wm * 16 + (lane & 15)) * PP + ((lane >> 4) & 1) * 16;
    const unsigned bV = (wn * 64 + ((lane >> 4) & 1) * 8 + (lane & 7)) * PP
                      + ((lane >> 3) & 1) * 16;

    // ---- load Q tile (64 rows x 128 dims, hi+lo) via cp.async ----
    {
        const int c = t & 15;            // 16B chunk within row
        #pragma unroll
        for (int pass = 0; pass < 4; ++pass) {
            const int r = (t >> 4) + pass * 16;
            const size_t gq = headoff + (size_t)(q0 + r) * HID + c * 8;
            cp16(smem + SQ_HI + r * QP + c * 16, qhi + gq);
            cp16(smem + SQ_LO + r * QP + c * 16, qlo + gq);
        }
    }
    CP_COMMIT();

    float o[8][4];
    #pragma unroll
    for (int nt = 0; nt < 8; ++nt)
        #pragma unroll
        for (int c = 0; c < 4; ++c) o[nt][c] = 0.f;
    float m_i[2] = {-1e30f, -1e30f};
    float l_i[2] = {0.f, 0.f};
    const float scale = 0.088388347648318447f;   // 1/sqrt(128)

    const int njt = 2 * (qt + 1);
    for (int j = 0; j < njt; ++j) {
        const int kbase = j * KT2;
        __syncthreads();   // previous tile's P/K/V reads + red arrays done

        // load K tile (32 x 128, hi+lo) via cp.async
        {
            const int c = t & 15;
            #pragma unroll
            for (int pass = 0; pass < 2; ++pass) {
                const int r = (t >> 4) + pass * 16;
                const size_t gk = headoff + (size_t)(kbase + r) * HID + c * 8;
                cp16(smem + SK_HI + r * QP + c * 16, khi + gk);
                cp16(smem + SK_LO + r * QP + c * 16, klo + gk);
            }
        }
        CP_COMMIT();
        // load V tile transposed: Vt[d][key], hi+lo (plain ld/st)
        {
            const int key = t >> 3;          // 0..31
            const int d0  = (t & 7) * 16;    // 16 dims per thread
            const size_t gv = headoff + (size_t)(kbase + key) * HID + d0;
            uint4 vh0 = *(const uint4*)(vhi + gv);
            uint4 vh1 = *(const uint4*)(vhi + gv + 8);
            uint4 vl0 = *(const uint4*)(vlo + gv);
            uint4 vl1 = *(const uint4*)(vlo + gv + 8);
            const __nv_bfloat16* ph = (const __nv_bfloat16*)&vh0;
            const __nv_bfloat16* pl = (const __nv_bfloat16*)&vl0;
            #pragma unroll
            for (int i = 0; i < 16; ++i) {
                *(__nv_bfloat16*)(sm + SVT_HI + (d0 + i) * PP + key * 2) = ph[i];
                *(__nv_bfloat16*)(sm + SVT_LO + (d0 + i) * PP + key * 2) = pl[i];
            }
            (void)vh1; (void)vl1;  // ph/pl alias both uint4s contiguously? no — handle below
            const __nv_bfloat16* ph1 = (const __nv_bfloat16*)&vh1;
            const __nv_bfloat16* pl1 = (const __nv_bfloat16*)&vl1;
            #pragma unroll
            for (int i = 0; i < 8; ++i) {
                *(__nv_bfloat16*)(sm + SVT_HI + (d0 + 8 + i) * PP + key * 2) = ph1[i];
                *(__nv_bfloat16*)(sm + SVT_LO + (d0 + 8 + i) * PP + key * 2) = pl1[i];
            }
        }
        CP_WAIT(0);
        __syncthreads();   // K, V (and Q on first iter) resident

        // ---- S = Q K^T : warp computes 16 rows x 16 keys ----
        float s[2][4];
        #pragma unroll
        for (int nt = 0; nt < 2; ++nt)
            #pragma unroll
            for (int c = 0; c < 4; ++c) s[nt][c] = 0.f;

        #pragma unroll
        for (int ks = 0; ks < 8; ++ks) {
            const unsigned ko = ks * 32;
            unsigned qh[4], ql[4], kh[4], kl[4];
            ldm4(qh, smem + SQ_HI + aQ + ko);
            ldm4(ql, smem + SQ_LO + aQ + ko);
            ldm4(kh, smem + SK_HI + bK + ko);
            ldm4(kl, smem + SK_LO + bK + ko);
            #pragma unroll
            for (int nt = 0; nt < 2; ++nt)
                mma_bf16(s[nt], qh, &kh[nt * 2]);
            #pragma unroll
            for (int nt = 0; nt < 2; ++nt)
                mma_bf16(s[nt], qh, &kl[nt * 2]);
            #pragma unroll
            for (int nt = 0; nt < 2; ++nt)
                mma_bf16(s[nt], ql, &kh[nt * 2]);
        }

        // scale + causal mask
        const bool maskt = (kbase + KT2 - 1 > q0 + wm * 16);
        #pragma unroll
        for (int nt = 0; nt < 2; ++nt)
            #pragma unroll
            for (int c = 0; c < 4; ++c) {
                float x = s[nt][c] * scale;
                if (maskt) {
                    const int col = kbase + wn * 16 + nt * 8 + tig * 2 + (c & 1);
                    const int row = q0 + wm * 16 + g + 8 * (c >> 1);
                    if (col > row) x = -1e30f;
                }
                s[nt][c] = x;
            }

        // per-thread row max (rows g, g+8) -> quad reduce -> smem partial
        float mx0 = fmaxf(fmaxf(s[0][0], s[0][1]), fmaxf(s[1][0], s[1][1]));
        float mx1 = fmaxf(fmaxf(s[0][2], s[0][3]), fmaxf(s[1][2], s[1][3]));
        mx0 = fmaxf(mx0, __shfl_xor_sync(0xffffffffu, mx0, 1));
        mx0 = fmaxf(mx0, __shfl_xor_sync(0xffffffffu, mx0, 2));
        mx1 = fmaxf(mx1, __shfl_xor_sync(0xffffffffu, mx1, 1));
        mx1 = fmaxf(mx1, __shfl_xor_sync(0xffffffffu, mx1, 2));
        if (tig == 0) {
            redmx[wn * 64 + wm * 16 + g]     = mx0;
            redmx[wn * 64 + wm * 16 + g + 8] = mx1;
        }
        __syncthreads();

        const int r0 = wm * 16 + g, r1 = r0 + 8;
        const float mg0 = fmaxf(redmx[r0], redmx[64 + r0]);
        const float mg1 = fmaxf(redmx[r1], redmx[64 + r1]);
        const float mn0 = fmaxf(m_i[0], mg0);
        const float mn1 = fmaxf(m_i[1], mg1);
        const float cr0 = __expf(m_i[0] - mn0);
        const float cr1 = __expf(m_i[1] - mn1);

        // P = exp(s - m), write hi/lo to smem, partial row sums
        float sum0 = 0.f, sum1 = 0.f;
        #pragma unroll
        for (int nt = 0; nt < 2; ++nt) {
            const int keyc = wn * 16 + nt * 8 + tig * 2;
            float p0 = __expf(s[nt][0] - mn0);
            float p1 = __expf(s[nt][1] - mn0);
            float p2 = __expf(s[nt][2] - mn1);
            float p3 = __expf(s[nt][3] - mn1);
            sum0 += p0 + p1; sum1 += p2 + p3;
            __nv_bfloat162 l0, l1;
            __nv_bfloat162 h0 = split_pair(p0, p1, &l0);
            __nv_bfloat162 h1 = split_pair(p2, p3, &l1);
            *(__nv_bfloat162*)(sm + SP_HI + r0 * PP + keyc * 2) = h0;
            *(__nv_bfloat162*)(sm + SP_LO + r0 * PP + keyc * 2) = l0;
            *(__nv_bfloat162*)(sm + SP_HI + r1 * PP + keyc * 2) = h1;
            *(__nv_bfloat162*)(sm + SP_LO + r1 * PP + keyc * 2) = l1;
        }
        sum0 += __shfl_xor_sync(0xffffffffu, sum0, 1);
        sum0 += __shfl_xor_sync(0xffffffffu, sum0, 2);
        sum1 += __shfl_xor_sync(0xffffffffu, sum1, 1);
        sum1 += __shfl_xor_sync(0xffffffffu, sum1, 2);
        if (tig == 0) {
            redsm[wn * 64 + r0] = sum0;
            redsm[wn * 64 + r1] = sum1;
        }
        __syncthreads();   // P + sums visible

        l_i[0] = l_i[0] * cr0 + redsm[r0] + redsm[64 + r0];
        l_i[1] = l_i[1] * cr1 + redsm[r1] + redsm[64 + r1];
        m_i[0] = mn0; m_i[1] = mn1;
        #pragma unroll
        for (int nt = 0; nt < 8; ++nt) {
            o[nt][0] *= cr0; o[nt][1] *= cr0;
            o[nt][2] *= cr1; o[nt][3] *= cr1;
        }

        // ---- O += P V : warp 16 rows x 64 d-cols, K=32 keys ----
        #pragma unroll
        for (int ks = 0; ks < 2; ++ks) {
            const unsigned ko = ks * 32;
            unsigned ph[4], pl[4], vh[4][4], vl[4][4];
            ldm4(ph, smem + SP_HI + aP + ko);
            ldm4(pl, smem + SP_LO + aP + ko);
            #pragma unroll
            for (int p = 0; p < 4; ++p) {
                ldm4(vh[p], smem + SVT_HI + bV + p * (16 * PP) + ko);
                ldm4(vl[p], smem + SVT_LO + bV + p * (16 * PP) + ko);
            }
            #pragma unroll
            for (int nt = 0; nt < 8; ++nt)
                mma_bf16(o[nt], ph, &vh[nt >> 1][(nt & 1) * 2]);
            #pragma unroll
            for (int nt = 0; nt < 8; ++nt)
                mma_bf16(o[nt], ph, &vl[nt >> 1][(nt & 1) * 2]);
            #pragma unroll
            for (int nt = 0; nt < 8; ++nt)
                mma_bf16(o[nt], pl, &vh[nt >> 1][(nt & 1) * 2]);
        }
    }

    // normalize + write bf16 hi/lo
    const float inv0 = 1.f / l_i[0];
    const float inv1 = 1.f / l_i[1];
    const int row0 = q0 + wm * 16 + g;
    #pragma unroll
    for (int nt = 0; nt < 8; ++nt) {
        const int col = wn * 64 + nt * 8 + tig * 2;
        const size_t i0 = headoff + (size_t)row0 * HID + col;
        const size_t i1 = headoff + (size_t)(row0 + 8) * HID + col;
        __nv_bfloat162 l0, l1;
        __nv_bfloat162 h0 = split_pair(o[nt][0] * inv0, o[nt][1] * inv0, &l0);
        __nv_bfloat162 h1 = split_pair(o[nt][2] * inv1, o[nt][3] * inv1, &l1);
        *(__nv_bfloat162*)(ohi + i0) = h0;
        *(__nv_bfloat162*)(olo + i0) = l0;
        *(__nv_bfloat162*)(ohi + i1) = h1;
        *(__nv_bfloat162*)(olo + i1) = l1;
    }
}

// ---------------------------------------------------------------------------
extern "C" void kernel_launch(void* const* d_in, const int* in_sizes, int n_in,
                              void* d_out, int out_size)
{
    (void)in_sizes; (void)n_in; (void)out_size;
    const float* x  = (const float*)d_in[0];
    const float* fr = (const float*)d_in[1];
    const float* w0 = (const float*)d_in[2];
    const float* w1 = (const float*)d_in[3];
    const float* w2 = (const float*)d_in[4];
    const float* w3 = (const float*)d_in[5];
    float* out = (float*)d_out;

    __nv_bfloat16 *xhi, *xlo, *whi, *wlo;
    __nv_bfloat16 *qhi, *qlo, *khi, *klo, *vhi, *vlo, *aohi, *aolo;
    cudaGetSymbolAddress((void**)&xhi,  g_x_hi);
    cudaGetSymbolAddress((void**)&xlo,  g_x_lo);
    cudaGetSymbolAddress((void**)&whi,  g_w_hi);
    cudaGetSymbolAddress((void**)&wlo,  g_w_lo);
    cudaGetSymbolAddress((void**)&qhi,  g_q_hi);
    cudaGetSymbolAddress((void**)&qlo,  g_q_lo);
    cudaGetSymbolAddress((void**)&khi,  g_k_hi);
    cudaGetSymbolAddress((void**)&klo,  g_k_lo);
    cudaGetSymbolAddress((void**)&vhi,  g_v_hi);
    cudaGetSymbolAddress((void**)&vlo,  g_v_lo);
    cudaGetSymbolAddress((void**)&aohi, g_ao_hi);
    cudaGetSymbolAddress((void**)&aolo, g_ao_lo);

    cudaFuncSetAttribute(gemm_qkv,    cudaFuncAttributeMaxDynamicSharedMemorySize, GEMM_SMEM);
    cudaFuncSetAttribute(gemm_single, cudaFuncAttributeMaxDynamicSharedMemorySize, GEMM_SMEM);
    cudaFuncSetAttribute(attn_mma,    cudaFuncAttributeMaxDynamicSharedMemorySize, ATTN_SMEM);

    split_all<<<(TOT4 + 255) / 256, 256>>>(x, w0, w1, w2, w3, xhi, xlo, whi, wlo);

    dim3 gqkv(HID / 128, MROWS / 128, 3);
    gemm_qkv<<<gqkv, 256, GEMM_SMEM>>>(xhi, xlo, whi, wlo,
                                       qhi, qlo, khi, klo, vhi, vlo, fr);

    attn_mma<<<dim3(SEQ / 64, BATCH * NHEAD), 256, ATTN_SMEM>>>(
        qhi, qlo, khi, klo, vhi, vlo, aohi, aolo);

    dim3 gg(HID / 128, MROWS / 128);
    gemm_single<<<gg, 256, GEMM_SMEM>>>(aohi, aolo, whi + 3 * (size_t)HID * HID,
                                        wlo + 3 * (size_t)HID * HID, out);
}

// round 13
// speedup vs baseline: 1.8089x; 1.2064x over previous
#include <cuda_runtime.h>
#include <cuda_bf16.h>

#define BATCH 2
#define SEQ   2048
#define HID   2048
#define NHEAD 16
#define DK    128
#define MROWS (BATCH*SEQ)

// ---------------- scratch (allocation-free) ----------------
__device__ __nv_bfloat16 g_x_hi[(size_t)MROWS * HID];
__device__ __nv_bfloat16 g_x_lo[(size_t)MROWS * HID];
__device__ __nv_bfloat16 g_w_hi[4][(size_t)HID * HID];
__device__ __nv_bfloat16 g_w_lo[4][(size_t)HID * HID];
__device__ __nv_bfloat16 g_q_hi[(size_t)MROWS * HID];
__device__ __nv_bfloat16 g_q_lo[(size_t)MROWS * HID];
__device__ __nv_bfloat16 g_k_hi[(size_t)MROWS * HID];
__device__ __nv_bfloat16 g_k_lo[(size_t)MROWS * HID];
__device__ __nv_bfloat16 g_v_hi[(size_t)MROWS * HID];
__device__ __nv_bfloat16 g_v_lo[(size_t)MROWS * HID];
__device__ __nv_bfloat16 g_ao_hi[(size_t)MROWS * HID];
__device__ __nv_bfloat16 g_ao_lo[(size_t)MROWS * HID];

// ---------------- PTX helpers (sm_80-era, nothing 'a'-gated) ----------------
__device__ __forceinline__ unsigned smem_u32(const void* p) {
    unsigned a;
    asm("{ .reg .u64 t; cvta.to.shared.u64 t, %1; cvt.u32.u64 %0, t; }" : "=r"(a) : "l"(p));
    return a;
}
__device__ __forceinline__ void cp16(unsigned s, const void* g) {
    asm volatile("cp.async.cg.shared.global [%0], [%1], 16;" :: "r"(s), "l"(g));
}
#define CP_COMMIT() asm volatile("cp.async.commit_group;" ::: "memory")
#define CP_WAIT(n)  asm volatile("cp.async.wait_group %0;" :: "n"(n) : "memory")

__device__ __forceinline__ void ldm4(unsigned* r, unsigned addr) {
    asm volatile("ldmatrix.sync.aligned.m8n8.x4.shared.b16 {%0,%1,%2,%3}, [%4];"
        : "=r"(r[0]), "=r"(r[1]), "=r"(r[2]), "=r"(r[3]) : "r"(addr));
}
__device__ __forceinline__ void ldm4t(unsigned* r, unsigned addr) {
    asm volatile("ldmatrix.sync.aligned.m8n8.x4.trans.shared.b16 {%0,%1,%2,%3}, [%4];"
        : "=r"(r[0]), "=r"(r[1]), "=r"(r[2]), "=r"(r[3]) : "r"(addr));
}
__device__ __forceinline__ void mma_bf16(float* d, const unsigned* a, const unsigned* b) {
    asm volatile(
        "mma.sync.aligned.m16n8k16.row.col.f32.bf16.bf16.f32 "
        "{%0,%1,%2,%3}, {%4,%5,%6,%7}, {%8,%9}, {%0,%1,%2,%3};"
        : "+f"(d[0]), "+f"(d[1]), "+f"(d[2]), "+f"(d[3])
        : "r"(a[0]), "r"(a[1]), "r"(a[2]), "r"(a[3]), "r"(b[0]), "r"(b[1]));
}

__device__ __forceinline__ __nv_bfloat162 split_pair(float a0, float a1,
                                                     __nv_bfloat162* lo_out) {
    __nv_bfloat16 h0 = __float2bfloat16(a0);
    __nv_bfloat16 h1 = __float2bfloat16(a1);
    *lo_out = __nv_bfloat162(__float2bfloat16(a0 - __bfloat162float(h0)),
                             __float2bfloat16(a1 - __bfloat162float(h1)));
    return __nv_bfloat162(h0, h1);
}

// ---------------- fused fp32 -> bf16 hi/lo split (ONE launch) ----------------
#define X4   ((MROWS * HID) / 4)
#define W4   ((HID * HID) / 4)
#define TOT4 (X4 + 4 * W4)

__global__ __launch_bounds__(256)
void split_all(const float* __restrict__ x,
               const float* __restrict__ w0, const float* __restrict__ w1,
               const float* __restrict__ w2, const float* __restrict__ w3,
               __nv_bfloat16* __restrict__ xhi, __nv_bfloat16* __restrict__ xlo,
               __nv_bfloat16* __restrict__ whi, __nv_bfloat16* __restrict__ wlo)
{
    int i = blockIdx.x * 256 + threadIdx.x;
    if (i >= TOT4) return;
    const float* src;
    __nv_bfloat16 *hi, *lo;
    int idx;
    if (i < X4) {
        src = x; hi = xhi; lo = xlo; idx = i;
    } else {
        int j = i - X4;
        int wi = j / W4;
        idx = j - wi * W4;
        const float* ws[4] = {w0, w1, w2, w3};
        src = ws[wi];
        hi = whi + (size_t)wi * HID * HID;
        lo = wlo + (size_t)wi * HID * HID;
    }
    float4 v = ((const float4*)src)[idx];
    __nv_bfloat162 l0, l1;
    __nv_bfloat162 h0 = split_pair(v.x, v.y, &l0);
    __nv_bfloat162 h1 = split_pair(v.z, v.w, &l1);
    ((__nv_bfloat162*)hi)[2*idx+0] = h0;
    ((__nv_bfloat162*)hi)[2*idx+1] = h1;
    ((__nv_bfloat162*)lo)[2*idx+0] = l0;
    ((__nv_bfloat162*)lo)[2*idx+1] = l1;
}

// ---------------- mma.sync GEMM body ----------------
#define BKI 32
#define ROWB 80
#define ARR_BYTES (128 * ROWB)
#define OFF_AHI 0
#define OFF_ALO (1 * ARR_BYTES)
#define OFF_BHI (2 * ARR_BYTES)
#define OFF_BLO (3 * ARR_BYTES)
#define STG_BYTES (4 * ARR_BYTES)
#define GEMM_SMEM (2 * STG_BYTES)
#define NKIT (HID / BKI)

__device__ __forceinline__ void gemm_load_stage(
    const __nv_bfloat16* __restrict__ Ahi, const __nv_bfloat16* __restrict__ Alo,
    const __nv_bfloat16* __restrict__ Bhi, const __nv_bfloat16* __restrict__ Blo,
    int rowBase, int colBase, int k0, unsigned stage, int t)
{
    const int r    = t >> 1;
    const int half = t & 1;
    const size_t ga = (size_t)(rowBase + r) * HID + k0 + half * 16;
    const size_t gb = (size_t)(colBase + r) * HID + k0 + half * 16;
    const unsigned so = r * ROWB + half * 32;
    cp16(stage + OFF_AHI + so,      Ahi + ga);
    cp16(stage + OFF_AHI + so + 16, Ahi + ga + 8);
    cp16(stage + OFF_ALO + so,      Alo + ga);
    cp16(stage + OFF_ALO + so + 16, Alo + ga + 8);
    cp16(stage + OFF_BHI + so,      Bhi + gb);
    cp16(stage + OFF_BHI + so + 16, Bhi + gb + 8);
    cp16(stage + OFF_BLO + so,      Blo + gb);
    cp16(stage + OFF_BLO + so + 16, Blo + gb + 8);
}

// If Cf != nullptr: write fp32. Else write bf16 hi/lo split to Chi/Clo.
__device__ __forceinline__ void gemm_body(
    const __nv_bfloat16* __restrict__ Ahi, const __nv_bfloat16* __restrict__ Alo,
    const __nv_bfloat16* __restrict__ Bhi, const __nv_bfloat16* __restrict__ Blo,
    float* __restrict__ Cf,
    __nv_bfloat16* __restrict__ Chi, __nv_bfloat16* __restrict__ Clo,
    const float* __restrict__ freqs, int do_rope)
{
    extern __shared__ char sm[];
    const unsigned smem = smem_u32(sm);
    const int t    = threadIdx.x;
    const int wid  = t >> 5;
    const int lane = t & 31;
    const int wm   = wid & 1;
    const int wn   = wid >> 1;
    const int rowBase = blockIdx.y * 128;
    const int colBase = blockIdx.x * 128;

    const unsigned aOff = (wm * 64 + (lane & 15)) * ROWB + ((lane >> 4) & 1) * 16;
    const unsigned bOff = (wn * 32 + ((lane >> 4) & 1) * 8 + (lane & 7)) * ROWB
                        + ((lane >> 3) & 1) * 16;

    float acc[4][4][4];
    #pragma unroll
    for (int mt = 0; mt < 4; ++mt)
        #pragma unroll
        for (int nt = 0; nt < 4; ++nt)
            #pragma unroll
            for (int c = 0; c < 4; ++c) acc[mt][nt][c] = 0.f;

    gemm_load_stage(Ahi, Alo, Bhi, Blo, rowBase, colBase, 0, smem, t);
    CP_COMMIT();

    for (int it = 0; it < NKIT; ++it) {
        const unsigned cur = smem + (it & 1) * STG_BYTES;
        if (it + 1 < NKIT) {
            CP_WAIT(0);
            __syncthreads();   // stage `it` resident AND all prior reads done
            gemm_load_stage(Ahi, Alo, Bhi, Blo, rowBase, colBase, (it + 1) * BKI,
                            smem + ((it + 1) & 1) * STG_BYTES, t);
            CP_COMMIT();
        } else {
            CP_WAIT(0);
            __syncthreads();
        }

        #pragma unroll
        for (int ks = 0; ks < 2; ++ks) {
            const unsigned kofs = ks * 32;
            unsigned ah[4][4], al[4][4], bh[2][4], bl[2][4];
            #pragma unroll
            for (int mt = 0; mt < 4; ++mt) {
                ldm4(ah[mt], cur + OFF_AHI + aOff + mt * (16 * ROWB) + kofs);
                ldm4(al[mt], cur + OFF_ALO + aOff + mt * (16 * ROWB) + kofs);
            }
            #pragma unroll
            for (int p = 0; p < 2; ++p) {
                ldm4(bh[p], cur + OFF_BHI + bOff + p * (16 * ROWB) + kofs);
                ldm4(bl[p], cur + OFF_BLO + bOff + p * (16 * ROWB) + kofs);
            }
            #pragma unroll
            for (int mt = 0; mt < 4; ++mt)
                #pragma unroll
                for (int nt = 0; nt < 4; ++nt)
                    mma_bf16(acc[mt][nt], ah[mt], &bh[nt >> 1][(nt & 1) * 2]);
            #pragma unroll
            for (int mt = 0; mt < 4; ++mt)
                #pragma unroll
                for (int nt = 0; nt < 4; ++nt)
                    mma_bf16(acc[mt][nt], ah[mt], &bl[nt >> 1][(nt & 1) * 2]);
            #pragma unroll
            for (int mt = 0; mt < 4; ++mt)
                #pragma unroll
                for (int nt = 0; nt < 4; ++nt)
                    mma_bf16(acc[mt][nt], al[mt], &bh[nt >> 1][(nt & 1) * 2]);
        }
    }

    const int g   = lane >> 2;
    const int tig = lane & 3;
    #pragma unroll
    for (int mt = 0; mt < 4; ++mt) {
        #pragma unroll
        for (int nt = 0; nt < 4; ++nt) {
            const int m0 = rowBase + wm * 64 + mt * 16 + g;
            const int n0 = colBase + wn * 32 + nt * 8 + tig * 2;
            float v0 = acc[mt][nt][0], v1 = acc[mt][nt][1];
            float v2 = acc[mt][nt][2], v3 = acc[mt][nt][3];
            if (do_rope) {
                const int d = n0 & (DK - 1);
                const int s0 = m0 & (SEQ - 1);
                const int s1 = (m0 + 8) & (SEQ - 1);
                const float cs0 = freqs[s0 * DK + d], sn0 = freqs[s0 * DK + d + 1];
                const float cs1 = freqs[s1 * DK + d], sn1 = freqs[s1 * DK + d + 1];
                float r0 = v0 * cs0 - v1 * sn0, r1 = v0 * sn0 + v1 * cs0;
                float r2 = v2 * cs1 - v3 * sn1, r3 = v2 * sn1 + v3 * cs1;
                v0 = r0; v1 = r1; v2 = r2; v3 = r3;
            }
            if (Cf) {
                *(float2*)(Cf + (size_t)m0 * HID + n0)       = make_float2(v0, v1);
                *(float2*)(Cf + (size_t)(m0 + 8) * HID + n0) = make_float2(v2, v3);
            } else {
                __nv_bfloat162 l0, l1;
                __nv_bfloat162 h0 = split_pair(v0, v1, &l0);
                __nv_bfloat162 h1 = split_pair(v2, v3, &l1);
                *(__nv_bfloat162*)(Chi + (size_t)m0 * HID + n0)       = h0;
                *(__nv_bfloat162*)(Chi + (size_t)(m0 + 8) * HID + n0) = h1;
                *(__nv_bfloat162*)(Clo + (size_t)m0 * HID + n0)       = l0;
                *(__nv_bfloat162*)(Clo + (size_t)(m0 + 8) * HID + n0) = l1;
            }
        }
    }
}

__global__ __launch_bounds__(256, 2)
void gemm_qkv(const __nv_bfloat16* __restrict__ xhi, const __nv_bfloat16* __restrict__ xlo,
              const __nv_bfloat16* __restrict__ whi, const __nv_bfloat16* __restrict__ wlo,
              __nv_bfloat16* __restrict__ qhi, __nv_bfloat16* __restrict__ qlo,
              __nv_bfloat16* __restrict__ khi, __nv_bfloat16* __restrict__ klo,
              __nv_bfloat16* __restrict__ vhi, __nv_bfloat16* __restrict__ vlo,
              const float* __restrict__ freqs)
{
    const int z = blockIdx.z;
    const __nv_bfloat16* bh = whi + (size_t)z * HID * HID;
    const __nv_bfloat16* bl = wlo + (size_t)z * HID * HID;
    __nv_bfloat16* Chi = (z == 0) ? qhi : ((z == 1) ? khi : vhi);
    __nv_bfloat16* Clo = (z == 0) ? qlo : ((z == 1) ? klo : vlo);
    gemm_body(xhi, xlo, bh, bl, nullptr, Chi, Clo, freqs, z < 2 ? 1 : 0);
}

__global__ __launch_bounds__(256, 2)
void gemm_single(const __nv_bfloat16* __restrict__ ahi, const __nv_bfloat16* __restrict__ alo,
                 const __nv_bfloat16* __restrict__ bhi, const __nv_bfloat16* __restrict__ blo,
                 float* __restrict__ C)
{
    gemm_body(ahi, alo, bhi, blo, C, nullptr, nullptr, nullptr, 0);
}

// ---------------------------------------------------------------------------
// Tensorized flash attention (bf16 hi/lo, 3-product), fp32 softmax/O state.
// Block: 64 q-rows x one head. 8 warps: wm=wid&3 (16-row groups),
// wn=wid>>2 (key/column halves). KT=32 keys per tile.
// V kept ROW-major [key][dim]; PV B-fragments via ldmatrix.x4.trans.
// Pitches: 272B for 128-dim rows (Q,K,V), 80B for 32-key rows (P).
// ---------------------------------------------------------------------------
#define KT2    32
#define QP     272
#define PP     80
#define SQ_HI  0
#define SQ_LO  (SQ_HI + 64 * QP)        // 17408
#define SK_HI  (SQ_LO + 64 * QP)        // 34816
#define SK_LO  (SK_HI + 32 * QP)        // 43520
#define SV_HI  (SK_LO + 32 * QP)        // 52224
#define SV_LO  (SV_HI + 32 * QP)        // 60928
#define SP_HI  (SV_LO + 32 * QP)        // 69632
#define SP_LO  (SP_HI + 64 * PP)        // 74752
#define RED_MX (SP_LO + 64 * PP)        // 79872
#define RED_SM (RED_MX + 2 * 64 * 4)    // 80384
#define ATTN_SMEM (RED_SM + 2 * 64 * 4) // 80896

__global__ __launch_bounds__(256, 2)
void attn_mma(const __nv_bfloat16* __restrict__ qhi, const __nv_bfloat16* __restrict__ qlo,
              const __nv_bfloat16* __restrict__ khi, const __nv_bfloat16* __restrict__ klo,
              const __nv_bfloat16* __restrict__ vhi, const __nv_bfloat16* __restrict__ vlo,
              __nv_bfloat16* __restrict__ ohi, __nv_bfloat16* __restrict__ olo)
{
    extern __shared__ char sm[];
    const unsigned smem = smem_u32(sm);
    float* redmx = (float*)(sm + RED_MX);
    float* redsm = (float*)(sm + RED_SM);

    const int t    = threadIdx.x;
    const int wid  = t >> 5;
    const int lane = t & 31;
    const int wm   = wid & 3;
    const int wn   = wid >> 2;
    const int g    = lane >> 2;
    const int tig  = lane & 3;

    const int qt = gridDim.x - 1 - blockIdx.x;   // longest tiles first
    const int b  = blockIdx.y >> 4;
    const int h  = blockIdx.y & 15;
    const int q0 = qt * 64;
    const size_t headoff = (size_t)b * SEQ * HID + (size_t)h * DK;

    // fragment base offsets
    const unsigned aQ = (wm * 16 + (lane & 15)) * QP + ((lane >> 4) & 1) * 16;
    const unsigned bK = (wn * 16 + ((lane >> 4) & 1) * 8 + (lane & 7)) * QP
                      + ((lane >> 3) & 1) * 16;
    const unsigned aP = (wm * 16 + (lane & 15)) * PP + ((lane >> 4) & 1) * 16;
    // V trans fragment: k-rows addressing. matrices: (k0-7,n0-7),(k8-15,n0-7),
    // (k0-7,n8-15),(k8-15,n8-15); n8 block offset = 16B; warp col group = 128B.
    const unsigned bVt = ((lane & 7) + ((lane >> 3) & 1) * 8) * QP
                       + ((lane >> 4) & 1) * 16 + wn * 128;

    // ---- load Q tile (64 rows x 128 dims, hi+lo) via cp.async ----
    {
        const int c = t & 15;
        #pragma unroll
        for (int pass = 0; pass < 4; ++pass) {
            const int r = (t >> 4) + pass * 16;
            const size_t gq = headoff + (size_t)(q0 + r) * HID + c * 8;
            cp16(smem + SQ_HI + r * QP + c * 16, qhi + gq);
            cp16(smem + SQ_LO + r * QP + c * 16, qlo + gq);
        }
    }
    CP_COMMIT();

    float o[8][4];
    #pragma unroll
    for (int nt = 0; nt < 8; ++nt)
        #pragma unroll
        for (int c = 0; c < 4; ++c) o[nt][c] = 0.f;
    float m_i[2] = {-1e30f, -1e30f};
    float l_i[2] = {0.f, 0.f};
    const float scale = 0.088388347648318447f;   // 1/sqrt(128)

    const int njt = 2 * (qt + 1);
    for (int j = 0; j < njt; ++j) {
        const int kbase = j * KT2;
        __syncthreads();   // previous tile's K/V/P reads done

        // load K + V tiles (32 x 128 each, hi+lo) via cp.async
        {
            const int c = t & 15;
            #pragma unroll
            for (int pass = 0; pass < 2; ++pass) {
                const int r = (t >> 4) + pass * 16;
                const size_t gk = headoff + (size_t)(kbase + r) * HID + c * 8;
                cp16(smem + SK_HI + r * QP + c * 16, khi + gk);
                cp16(smem + SK_LO + r * QP + c * 16, klo + gk);
                cp16(smem + SV_HI + r * QP + c * 16, vhi + gk);
                cp16(smem + SV_LO + r * QP + c * 16, vlo + gk);
            }
        }
        CP_COMMIT();
        CP_WAIT(0);
        __syncthreads();   // K, V (and Q on first iter) resident

        // ---- S = Q K^T : warp computes 16 rows x 16 keys ----
        float s[2][4];
        #pragma unroll
        for (int nt = 0; nt < 2; ++nt)
            #pragma unroll
            for (int c = 0; c < 4; ++c) s[nt][c] = 0.f;

        #pragma unroll
        for (int ks = 0; ks < 8; ++ks) {
            const unsigned ko = ks * 32;
            unsigned qh[4], ql[4], kh[4], kl[4];
            ldm4(qh, smem + SQ_HI + aQ + ko);
            ldm4(ql, smem + SQ_LO + aQ + ko);
            ldm4(kh, smem + SK_HI + bK + ko);
            ldm4(kl, smem + SK_LO + bK + ko);
            #pragma unroll
            for (int nt = 0; nt < 2; ++nt)
                mma_bf16(s[nt], qh, &kh[nt * 2]);
            #pragma unroll
            for (int nt = 0; nt < 2; ++nt)
                mma_bf16(s[nt], qh, &kl[nt * 2]);
            #pragma unroll
            for (int nt = 0; nt < 2; ++nt)
                mma_bf16(s[nt], ql, &kh[nt * 2]);
        }

        // scale + causal mask
        const bool maskt = (kbase + KT2 - 1 > q0 + wm * 16);
        #pragma unroll
        for (int nt = 0; nt < 2; ++nt)
            #pragma unroll
            for (int c = 0; c < 4; ++c) {
                float x = s[nt][c] * scale;
                if (maskt) {
                    const int col = kbase + wn * 16 + nt * 8 + tig * 2 + (c & 1);
                    const int row = q0 + wm * 16 + g + 8 * (c >> 1);
                    if (col > row) x = -1e30f;
                }
                s[nt][c] = x;
            }

        // row max: quad reduce -> smem partial -> merge across wn
        float mx0 = fmaxf(fmaxf(s[0][0], s[0][1]), fmaxf(s[1][0], s[1][1]));
        float mx1 = fmaxf(fmaxf(s[0][2], s[0][3]), fmaxf(s[1][2], s[1][3]));
        mx0 = fmaxf(mx0, __shfl_xor_sync(0xffffffffu, mx0, 1));
        mx0 = fmaxf(mx0, __shfl_xor_sync(0xffffffffu, mx0, 2));
        mx1 = fmaxf(mx1, __shfl_xor_sync(0xffffffffu, mx1, 1));
        mx1 = fmaxf(mx1, __shfl_xor_sync(0xffffffffu, mx1, 2));
        if (tig == 0) {
            redmx[wn * 64 + wm * 16 + g]     = mx0;
            redmx[wn * 64 + wm * 16 + g + 8] = mx1;
        }
        __syncthreads();

        const int r0 = wm * 16 + g, r1 = r0 + 8;
        const float mg0 = fmaxf(redmx[r0], redmx[64 + r0]);
        const float mg1 = fmaxf(redmx[r1], redmx[64 + r1]);
        const float mn0 = fmaxf(m_i[0], mg0);
        const float mn1 = fmaxf(m_i[1], mg1);
        const float cr0 = __expf(m_i[0] - mn0);
        const float cr1 = __expf(m_i[1] - mn1);

        // P = exp(s - m), hi/lo to smem, partial row sums
        float sum0 = 0.f, sum1 = 0.f;
        #pragma unroll
        for (int nt = 0; nt < 2; ++nt) {
            const int keyc = wn * 16 + nt * 8 + tig * 2;
            float p0 = __expf(s[nt][0] - mn0);
            float p1 = __expf(s[nt][1] - mn0);
            float p2 = __expf(s[nt][2] - mn1);
            float p3 = __expf(s[nt][3] - mn1);
            sum0 += p0 + p1; sum1 += p2 + p3;
            __nv_bfloat162 l0, l1;
            __nv_bfloat162 h0 = split_pair(p0, p1, &l0);
            __nv_bfloat162 h1 = split_pair(p2, p3, &l1);
            *(__nv_bfloat162*)(sm + SP_HI + r0 * PP + keyc * 2) = h0;
            *(__nv_bfloat162*)(sm + SP_LO + r0 * PP + keyc * 2) = l0;
            *(__nv_bfloat162*)(sm + SP_HI + r1 * PP + keyc * 2) = h1;
            *(__nv_bfloat162*)(sm + SP_LO + r1 * PP + keyc * 2) = l1;
        }
        sum0 += __shfl_xor_sync(0xffffffffu, sum0, 1);
        sum0 += __shfl_xor_sync(0xffffffffu, sum0, 2);
        sum1 += __shfl_xor_sync(0xffffffffu, sum1, 1);
        sum1 += __shfl_xor_sync(0xffffffffu, sum1, 2);
        if (tig == 0) {
            redsm[wn * 64 + r0] = sum0;
            redsm[wn * 64 + r1] = sum1;
        }
        __syncthreads();   // P + sums visible

        l_i[0] = l_i[0] * cr0 + redsm[r0] + redsm[64 + r0];
        l_i[1] = l_i[1] * cr1 + redsm[r1] + redsm[64 + r1];
        m_i[0] = mn0; m_i[1] = mn1;
        #pragma unroll
        for (int nt = 0; nt < 8; ++nt) {
            o[nt][0] *= cr0; o[nt][1] *= cr0;
            o[nt][2] *= cr1; o[nt][3] *= cr1;
        }

        // ---- O += P V : warp 16 rows x 64 d-cols, K=32 keys ----
        #pragma unroll
        for (int ks = 0; ks < 2; ++ks) {
            const unsigned ko  = ks * 32;            // P: 16 keys = 32B
            const unsigned kvo = ks * 16 * QP;       // V: 16 key-rows
            unsigned ph[4], pl[4], vh[4][4], vl[4][4];
            ldm4(ph, smem + SP_HI + aP + ko);
            ldm4(pl, smem + SP_LO + aP + ko);
            #pragma unroll
            for (int p = 0; p < 4; ++p) {
                ldm4t(vh[p], smem + SV_HI + bVt + kvo + p * 32);
                ldm4t(vl[p], smem + SV_LO + bVt + kvo + p * 32);
            }
            #pragma unroll
            for (int nt = 0; nt < 8; ++nt)
                mma_bf16(o[nt], ph, &vh[nt >> 1][(nt & 1) * 2]);
            #pragma unroll
            for (int nt = 0; nt < 8; ++nt)
                mma_bf16(o[nt], ph, &vl[nt >> 1][(nt & 1) * 2]);
            #pragma unroll
            for (int nt = 0; nt < 8; ++nt)
                mma_bf16(o[nt], pl, &vh[nt >> 1][(nt & 1) * 2]);
        }
    }

    // normalize + write bf16 hi/lo
    const float inv0 = 1.f / l_i[0];
    const float inv1 = 1.f / l_i[1];
    const int row0 = q0 + wm * 16 + g;
    #pragma unroll
    for (int nt = 0; nt < 8; ++nt) {
        const int col = wn * 64 + nt * 8 + tig * 2;
        const size_t i0 = headoff + (size_t)row0 * HID + col;
        const size_t i1 = headoff + (size_t)(row0 + 8) * HID + col;
        __nv_bfloat162 l0, l1;
        __nv_bfloat162 h0 = split_pair(o[nt][0] * inv0, o[nt][1] * inv0, &l0);
        __nv_bfloat162 h1 = split_pair(o[nt][2] * inv1, o[nt][3] * inv1, &l1);
        *(__nv_bfloat162*)(ohi + i0) = h0;
        *(__nv_bfloat162*)(olo + i0) = l0;
        *(__nv_bfloat162*)(ohi + i1) = h1;
        *(__nv_bfloat162*)(olo + i1) = l1;
    }
}

// ---------------------------------------------------------------------------
extern "C" void kernel_launch(void* const* d_in, const int* in_sizes, int n_in,
                              void* d_out, int out_size)
{
    (void)in_sizes; (void)n_in; (void)out_size;
    const float* x  = (const float*)d_in[0];
    const float* fr = (const float*)d_in[1];
    const float* w0 = (const float*)d_in[2];
    const float* w1 = (const float*)d_in[3];
    const float* w2 = (const float*)d_in[4];
    const float* w3 = (const float*)d_in[5];
    float* out = (float*)d_out;

    __nv_bfloat16 *xhi, *xlo, *whi, *wlo;
    __nv_bfloat16 *qhi, *qlo, *khi, *klo, *vhi, *vlo, *aohi, *aolo;
    cudaGetSymbolAddress((void**)&xhi,  g_x_hi);
    cudaGetSymbolAddress((void**)&xlo,  g_x_lo);
    cudaGetSymbolAddress((void**)&whi,  g_w_hi);
    cudaGetSymbolAddress((void**)&wlo,  g_w_lo);
    cudaGetSymbolAddress((void**)&qhi,  g_q_hi);
    cudaGetSymbolAddress((void**)&qlo,  g_q_lo);
    cudaGetSymbolAddress((void**)&khi,  g_k_hi);
    cudaGetSymbolAddress((void**)&klo,  g_k_lo);
    cudaGetSymbolAddress((void**)&vhi,  g_v_hi);
    cudaGetSymbolAddress((void**)&vlo,  g_v_lo);
    cudaGetSymbolAddress((void**)&aohi, g_ao_hi);
    cudaGetSymbolAddress((void**)&aolo, g_ao_lo);

    cudaFuncSetAttribute(gemm_qkv,    cudaFuncAttributeMaxDynamicSharedMemorySize, GEMM_SMEM);
    cudaFuncSetAttribute(gemm_single, cudaFuncAttributeMaxDynamicSharedMemorySize, GEMM_SMEM);
    cudaFuncSetAttribute(attn_mma,    cudaFuncAttributeMaxDynamicSharedMemorySize, ATTN_SMEM);

    split_all<<<(TOT4 + 255) / 256, 256>>>(x, w0, w1, w2, w3, xhi, xlo, whi, wlo);

    dim3 gqkv(HID / 128, MROWS / 128, 3);
    gemm_qkv<<<gqkv, 256, GEMM_SMEM>>>(xhi, xlo, whi, wlo,
                                       qhi, qlo, khi, klo, vhi, vlo, fr);

    attn_mma<<<dim3(SEQ / 64, BATCH * NHEAD), 256, ATTN_SMEM>>>(
        qhi, qlo, khi, klo, vhi, vlo, aohi, aolo);

    dim3 gg(HID / 128, MROWS / 128);
    gemm_single<<<gg, 256, GEMM_SMEM>>>(aohi, aolo, whi + 3 * (size_t)HID * HID,
                                        wlo + 3 * (size_t)HID * HID, out);
}

// round 14
// speedup vs baseline: 1.8228x; 1.0077x over previous
#include <cuda_runtime.h>
#include <cuda_bf16.h>

#define BATCH 2
#define SEQ   2048
#define HID   2048
#define NHEAD 16
#define DK    128
#define MROWS (BATCH*SEQ)

// ---------------- scratch (allocation-free) ----------------
__device__ __nv_bfloat16 g_x_hi[(size_t)MROWS * HID];
__device__ __nv_bfloat16 g_x_lo[(size_t)MROWS * HID];
__device__ __nv_bfloat16 g_w_hi[4][(size_t)HID * HID];
__device__ __nv_bfloat16 g_w_lo[4][(size_t)HID * HID];
__device__ __nv_bfloat16 g_q_hi[(size_t)MROWS * HID];
__device__ __nv_bfloat16 g_q_lo[(size_t)MROWS * HID];
__device__ __nv_bfloat16 g_k_hi[(size_t)MROWS * HID];
__device__ __nv_bfloat16 g_k_lo[(size_t)MROWS * HID];
__device__ __nv_bfloat16 g_v_hi[(size_t)MROWS * HID];
__device__ __nv_bfloat16 g_v_lo[(size_t)MROWS * HID];
__device__ __nv_bfloat16 g_ao_hi[(size_t)MROWS * HID];
__device__ __nv_bfloat16 g_ao_lo[(size_t)MROWS * HID];

// ---------------- PTX helpers (sm_80-era, nothing 'a'-gated) ----------------
__device__ __forceinline__ unsigned smem_u32(const void* p) {
    unsigned a;
    asm("{ .reg .u64 t; cvta.to.shared.u64 t, %1; cvt.u32.u64 %0, t; }" : "=r"(a) : "l"(p));
    return a;
}
__device__ __forceinline__ void cp16(unsigned s, const void* g) {
    asm volatile("cp.async.cg.shared.global [%0], [%1], 16;" :: "r"(s), "l"(g));
}
#define CP_COMMIT() asm volatile("cp.async.commit_group;" ::: "memory")
#define CP_WAIT(n)  asm volatile("cp.async.wait_group %0;" :: "n"(n) : "memory")

__device__ __forceinline__ void ldm4(unsigned* r, unsigned addr) {
    asm volatile("ldmatrix.sync.aligned.m8n8.x4.shared.b16 {%0,%1,%2,%3}, [%4];"
        : "=r"(r[0]), "=r"(r[1]), "=r"(r[2]), "=r"(r[3]) : "r"(addr));
}
__device__ __forceinline__ void ldm4t(unsigned* r, unsigned addr) {
    asm volatile("ldmatrix.sync.aligned.m8n8.x4.trans.shared.b16 {%0,%1,%2,%3}, [%4];"
        : "=r"(r[0]), "=r"(r[1]), "=r"(r[2]), "=r"(r[3]) : "r"(addr));
}
__device__ __forceinline__ void mma_bf16(float* d, const unsigned* a, const unsigned* b) {
    asm volatile(
        "mma.sync.aligned.m16n8k16.row.col.f32.bf16.bf16.f32 "
        "{%0,%1,%2,%3}, {%4,%5,%6,%7}, {%8,%9}, {%0,%1,%2,%3};"
        : "+f"(d[0]), "+f"(d[1]), "+f"(d[2]), "+f"(d[3])
        : "r"(a[0]), "r"(a[1]), "r"(a[2]), "r"(a[3]), "r"(b[0]), "r"(b[1]));
}

__device__ __forceinline__ __nv_bfloat162 split_pair(float a0, float a1,
                                                     __nv_bfloat162* lo_out) {
    __nv_bfloat16 h0 = __float2bfloat16(a0);
    __nv_bfloat16 h1 = __float2bfloat16(a1);
    *lo_out = __nv_bfloat162(__float2bfloat16(a0 - __bfloat162float(h0)),
                             __float2bfloat16(a1 - __bfloat162float(h1)));
    return __nv_bfloat162(h0, h1);
}

// ---------------- fused fp32 -> bf16 hi/lo split (ONE launch) ----------------
#define X4   ((MROWS * HID) / 4)
#define W4   ((HID * HID) / 4)
#define TOT4 (X4 + 4 * W4)

__global__ __launch_bounds__(256)
void split_all(const float* __restrict__ x,
               const float* __restrict__ w0, const float* __restrict__ w1,
               const float* __restrict__ w2, const float* __restrict__ w3,
               __nv_bfloat16* __restrict__ xhi, __nv_bfloat16* __restrict__ xlo,
               __nv_bfloat16* __restrict__ whi, __nv_bfloat16* __restrict__ wlo)
{
    int i = blockIdx.x * 256 + threadIdx.x;
    if (i >= TOT4) return;
    const float* src;
    __nv_bfloat16 *hi, *lo;
    int idx;
    if (i < X4) {
        src = x; hi = xhi; lo = xlo; idx = i;
    } else {
        int j = i - X4;
        int wi = j / W4;
        idx = j - wi * W4;
        const float* ws[4] = {w0, w1, w2, w3};
        src = ws[wi];
        hi = whi + (size_t)wi * HID * HID;
        lo = wlo + (size_t)wi * HID * HID;
    }
    float4 v = ((const float4*)src)[idx];
    __nv_bfloat162 l0, l1;
    __nv_bfloat162 h0 = split_pair(v.x, v.y, &l0);
    __nv_bfloat162 h1 = split_pair(v.z, v.w, &l1);
    ((__nv_bfloat162*)hi)[2*idx+0] = h0;
    ((__nv_bfloat162*)hi)[2*idx+1] = h1;
    ((__nv_bfloat162*)lo)[2*idx+0] = l0;
    ((__nv_bfloat162*)lo)[2*idx+1] = l1;
}

// ---------------- mma.sync GEMM: 3-stage cp.async pipeline ----------------
// 128x128 tile, BK=32, 8 warps (2m x 4n). Smem: 144B pitch rows, hi at +0,
// lo at +64 per row (bank step 36%32=4 => 8 ldmatrix rows conflict-free).
// Stage = A(128x144) + B(128x144) = 36864B; 3 stages = 110592B; 2 CTAs/SM.
#define BKI   32
#define PITCH 144
#define A_BLK (128 * PITCH)           // 18432
#define STAGE (2 * A_BLK)             // 36864
#define GEMM_SMEM (3 * STAGE)         // 110592
#define NKIT (HID / BKI)              // 64

__device__ __forceinline__ void gemm_load_stage(
    const __nv_bfloat16* __restrict__ Ahi, const __nv_bfloat16* __restrict__ Alo,
    const __nv_bfloat16* __restrict__ Bhi, const __nv_bfloat16* __restrict__ Blo,
    int rowBase, int colBase, int k0, unsigned stage, int t)
{
    const int r    = t >> 1;          // 0..127
    const int half = t & 1;           // which 32B half of the 64B payload
    const size_t ga = (size_t)(rowBase + r) * HID + k0 + half * 16;
    const size_t gb = (size_t)(colBase + r) * HID + k0 + half * 16;
    const unsigned sa = stage + r * PITCH + half * 32;
    const unsigned sb = sa + A_BLK;
    cp16(sa,          Ahi + ga);
    cp16(sa + 16,     Ahi + ga + 8);
    cp16(sa + 64,     Alo + ga);
    cp16(sa + 80,     Alo + ga + 8);
    cp16(sb,          Bhi + gb);
    cp16(sb + 16,     Bhi + gb + 8);
    cp16(sb + 64,     Blo + gb);
    cp16(sb + 80,     Blo + gb + 8);
}

// If Cf != nullptr: write fp32. Else write bf16 hi/lo split to Chi/Clo.
__device__ __forceinline__ void gemm_body(
    const __nv_bfloat16* __restrict__ Ahi, const __nv_bfloat16* __restrict__ Alo,
    const __nv_bfloat16* __restrict__ Bhi, const __nv_bfloat16* __restrict__ Blo,
    float* __restrict__ Cf,
    __nv_bfloat16* __restrict__ Chi, __nv_bfloat16* __restrict__ Clo,
    const float* __restrict__ freqs, int do_rope)
{
    extern __shared__ char sm[];
    const unsigned smem = smem_u32(sm);
    const int t    = threadIdx.x;
    const int wid  = t >> 5;
    const int lane = t & 31;
    const int wm   = wid & 1;
    const int wn   = wid >> 1;
    const int rowBase = blockIdx.y * 128;
    const int colBase = blockIdx.x * 128;

    // hi-fragment bases; lo is +64 within the same row
    const unsigned aOff = (wm * 64 + (lane & 15)) * PITCH + ((lane >> 4) & 1) * 16;
    const unsigned bOff = A_BLK + (wn * 32 + ((lane >> 4) & 1) * 8 + (lane & 7)) * PITCH
                        + ((lane >> 3) & 1) * 16;

    float acc[4][4][4];
    #pragma unroll
    for (int mt = 0; mt < 4; ++mt)
        #pragma unroll
        for (int nt = 0; nt < 4; ++nt)
            #pragma unroll
            for (int c = 0; c < 4; ++c) acc[mt][nt][c] = 0.f;

    // prologue: fill 2 stages
    gemm_load_stage(Ahi, Alo, Bhi, Blo, rowBase, colBase, 0,       smem,         t);
    CP_COMMIT();
    gemm_load_stage(Ahi, Alo, Bhi, Blo, rowBase, colBase, BKI,     smem + STAGE, t);
    CP_COMMIT();

    int s_cur = 0, s_pf = 2;
    for (int it = 0; it < NKIT; ++it) {
        CP_WAIT(1);            // stage `it` resident
        __syncthreads();       // + all warps done reading the buffer s_pf overwrites

        if (it + 2 < NKIT)
            gemm_load_stage(Ahi, Alo, Bhi, Blo, rowBase, colBase, (it + 2) * BKI,
                            smem + s_pf * STAGE, t);
        CP_COMMIT();           // unconditional: keeps group-count invariant

        const unsigned cur = smem + s_cur * STAGE;
        #pragma unroll
        for (int ks = 0; ks < 2; ++ks) {
            const unsigned kofs = ks * 32;
            unsigned ah[4][4], al[4][4], bh[2][4], bl[2][4];
            #pragma unroll
            for (int mt = 0; mt < 4; ++mt) {
                ldm4(ah[mt], cur + aOff + mt * (16 * PITCH) + kofs);
                ldm4(al[mt], cur + aOff + mt * (16 * PITCH) + kofs + 64);
            }
            #pragma unroll
            for (int p = 0; p < 2; ++p) {
                ldm4(bh[p], cur + bOff + p * (16 * PITCH) + kofs);
                ldm4(bl[p], cur + bOff + p * (16 * PITCH) + kofs + 64);
            }
            #pragma unroll
            for (int mt = 0; mt < 4; ++mt)
                #pragma unroll
                for (int nt = 0; nt < 4; ++nt)
                    mma_bf16(acc[mt][nt], ah[mt], &bh[nt >> 1][(nt & 1) * 2]);
            #pragma unroll
            for (int mt = 0; mt < 4; ++mt)
                #pragma unroll
                for (int nt = 0; nt < 4; ++nt)
                    mma_bf16(acc[mt][nt], ah[mt], &bl[nt >> 1][(nt & 1) * 2]);
            #pragma unroll
            for (int mt = 0; mt < 4; ++mt)
                #pragma unroll
                for (int nt = 0; nt < 4; ++nt)
                    mma_bf16(acc[mt][nt], al[mt], &bh[nt >> 1][(nt & 1) * 2]);
        }

        s_cur = (s_cur == 2) ? 0 : s_cur + 1;
        s_pf  = (s_pf  == 2) ? 0 : s_pf  + 1;
    }

    const int g   = lane >> 2;
    const int tig = lane & 3;
    #pragma unroll
    for (int mt = 0; mt < 4; ++mt) {
        #pragma unroll
        for (int nt = 0; nt < 4; ++nt) {
            const int m0 = rowBase + wm * 64 + mt * 16 + g;
            const int n0 = colBase + wn * 32 + nt * 8 + tig * 2;
            float v0 = acc[mt][nt][0], v1 = acc[mt][nt][1];
            float v2 = acc[mt][nt][2], v3 = acc[mt][nt][3];
            if (do_rope) {
                const int d = n0 & (DK - 1);
                const int s0 = m0 & (SEQ - 1);
                const int s1 = (m0 + 8) & (SEQ - 1);
                const float cs0 = freqs[s0 * DK + d], sn0 = freqs[s0 * DK + d + 1];
                const float cs1 = freqs[s1 * DK + d], sn1 = freqs[s1 * DK + d + 1];
                float r0 = v0 * cs0 - v1 * sn0, r1 = v0 * sn0 + v1 * cs0;
                float r2 = v2 * cs1 - v3 * sn1, r3 = v2 * sn1 + v3 * cs1;
                v0 = r0; v1 = r1; v2 = r2; v3 = r3;
            }
            if (Cf) {
                *(float2*)(Cf + (size_t)m0 * HID + n0)       = make_float2(v0, v1);
                *(float2*)(Cf + (size_t)(m0 + 8) * HID + n0) = make_float2(v2, v3);
            } else {
                __nv_bfloat162 l0, l1;
                __nv_bfloat162 h0 = split_pair(v0, v1, &l0);
                __nv_bfloat162 h1 = split_pair(v2, v3, &l1);
                *(__nv_bfloat162*)(Chi + (size_t)m0 * HID + n0)       = h0;
                *(__nv_bfloat162*)(Chi + (size_t)(m0 + 8) * HID + n0) = h1;
                *(__nv_bfloat162*)(Clo + (size_t)m0 * HID + n0)       = l0;
                *(__nv_bfloat162*)(Clo + (size_t)(m0 + 8) * HID + n0) = l1;
            }
        }
    }
}

__global__ __launch_bounds__(256, 2)
void gemm_qkv(const __nv_bfloat16* __restrict__ xhi, const __nv_bfloat16* __restrict__ xlo,
              const __nv_bfloat16* __restrict__ whi, const __nv_bfloat16* __restrict__ wlo,
              __nv_bfloat16* __restrict__ qhi, __nv_bfloat16* __restrict__ qlo,
              __nv_bfloat16* __restrict__ khi, __nv_bfloat16* __restrict__ klo,
              __nv_bfloat16* __restrict__ vhi, __nv_bfloat16* __restrict__ vlo,
              const float* __restrict__ freqs)
{
    const int z = blockIdx.z;
    const __nv_bfloat16* bh = whi + (size_t)z * HID * HID;
    const __nv_bfloat16* bl = wlo + (size_t)z * HID * HID;
    __nv_bfloat16* Chi = (z == 0) ? qhi : ((z == 1) ? khi : vhi);
    __nv_bfloat16* Clo = (z == 0) ? qlo : ((z == 1) ? klo : vlo);
    gemm_body(xhi, xlo, bh, bl, nullptr, Chi, Clo, freqs, z < 2 ? 1 : 0);
}

__global__ __launch_bounds__(256, 2)
void gemm_single(const __nv_bfloat16* __restrict__ ahi, const __nv_bfloat16* __restrict__ alo,
                 const __nv_bfloat16* __restrict__ bhi, const __nv_bfloat16* __restrict__ blo,
                 float* __restrict__ C)
{
    gemm_body(ahi, alo, bhi, blo, C, nullptr, nullptr, nullptr, 0);
}

// ---------------------------------------------------------------------------
// Tensorized flash attention (bf16 hi/lo, 3-product), fp32 softmax/O state.
// (unchanged from R13 — measured at its HMMA floor)
// ---------------------------------------------------------------------------
#define KT2    32
#define QP     272
#define PP     80
#define SQ_HI  0
#define SQ_LO  (SQ_HI + 64 * QP)
#define SK_HI  (SQ_LO + 64 * QP)
#define SK_LO  (SK_HI + 32 * QP)
#define SV_HI  (SK_LO + 32 * QP)
#define SV_LO  (SV_HI + 32 * QP)
#define SP_HI  (SV_LO + 32 * QP)
#define SP_LO  (SP_HI + 64 * PP)
#define RED_MX (SP_LO + 64 * PP)
#define RED_SM (RED_MX + 2 * 64 * 4)
#define ATTN_SMEM (RED_SM + 2 * 64 * 4)

__global__ __launch_bounds__(256, 2)
void attn_mma(const __nv_bfloat16* __restrict__ qhi, const __nv_bfloat16* __restrict__ qlo,
              const __nv_bfloat16* __restrict__ khi, const __nv_bfloat16* __restrict__ klo,
              const __nv_bfloat16* __restrict__ vhi, const __nv_bfloat16* __restrict__ vlo,
              __nv_bfloat16* __restrict__ ohi, __nv_bfloat16* __restrict__ olo)
{
    extern __shared__ char sm[];
    const unsigned smem = smem_u32(sm);
    float* redmx = (float*)(sm + RED_MX);
    float* redsm = (float*)(sm + RED_SM);

    const int t    = threadIdx.x;
    const int wid  = t >> 5;
    const int lane = t & 31;
    const int wm   = wid & 3;
    const int wn   = wid >> 2;
    const int g    = lane >> 2;
    const int tig  = lane & 3;

    const int qt = gridDim.x - 1 - blockIdx.x;
    const int b  = blockIdx.y >> 4;
    const int h  = blockIdx.y & 15;
    const int q0 = qt * 64;
    const size_t headoff = (size_t)b * SEQ * HID + (size_t)h * DK;

    const unsigned aQ = (wm * 16 + (lane & 15)) * QP + ((lane >> 4) & 1) * 16;
    const unsigned bK = (wn * 16 + ((lane >> 4) & 1) * 8 + (lane & 7)) * QP
                      + ((lane >> 3) & 1) * 16;
    const unsigned aP = (wm * 16 + (lane & 15)) * PP + ((lane >> 4) & 1) * 16;
    const unsigned bVt = ((lane & 7) + ((lane >> 3) & 1) * 8) * QP
                       + ((lane >> 4) & 1) * 16 + wn * 128;

    {
        const int c = t & 15;
        #pragma unroll
        for (int pass = 0; pass < 4; ++pass) {
            const int r = (t >> 4) + pass * 16;
            const size_t gq = headoff + (size_t)(q0 + r) * HID + c * 8;
            cp16(smem + SQ_HI + r * QP + c * 16, qhi + gq);
            cp16(smem + SQ_LO + r * QP + c * 16, qlo + gq);
        }
    }
    CP_COMMIT();

    float o[8][4];
    #pragma unroll
    for (int nt = 0; nt < 8; ++nt)
        #pragma unroll
        for (int c = 0; c < 4; ++c) o[nt][c] = 0.f;
    float m_i[2] = {-1e30f, -1e30f};
    float l_i[2] = {0.f, 0.f};
    const float scale = 0.088388347648318447f;

    const int njt = 2 * (qt + 1);
    for (int j = 0; j < njt; ++j) {
        const int kbase = j * KT2;
        __syncthreads();

        {
            const int c = t & 15;
            #pragma unroll
            for (int pass = 0; pass < 2; ++pass) {
                const int r = (t >> 4) + pass * 16;
                const size_t gk = headoff + (size_t)(kbase + r) * HID + c * 8;
                cp16(smem + SK_HI + r * QP + c * 16, khi + gk);
                cp16(smem + SK_LO + r * QP + c * 16, klo + gk);
                cp16(smem + SV_HI + r * QP + c * 16, vhi + gk);
                cp16(smem + SV_LO + r * QP + c * 16, vlo + gk);
            }
        }
        CP_COMMIT();
        CP_WAIT(0);
        __syncthreads();

        float s[2][4];
        #pragma unroll
        for (int nt = 0; nt < 2; ++nt)
            #pragma unroll
            for (int c = 0; c < 4; ++c) s[nt][c] = 0.f;

        #pragma unroll
        for (int ks = 0; ks < 8; ++ks) {
            const unsigned ko = ks * 32;
            unsigned qh[4], ql[4], kh[4], kl[4];
            ldm4(qh, smem + SQ_HI + aQ + ko);
            ldm4(ql, smem + SQ_LO + aQ + ko);
            ldm4(kh, smem + SK_HI + bK + ko);
            ldm4(kl, smem + SK_LO + bK + ko);
            #pragma unroll
            for (int nt = 0; nt < 2; ++nt)
                mma_bf16(s[nt], qh, &kh[nt * 2]);
            #pragma unroll
            for (int nt = 0; nt < 2; ++nt)
                mma_bf16(s[nt], qh, &kl[nt * 2]);
            #pragma unroll
            for (int nt = 0; nt < 2; ++nt)
                mma_bf16(s[nt], ql, &kh[nt * 2]);
        }

        const bool maskt = (kbase + KT2 - 1 > q0 + wm * 16);
        #pragma unroll
        for (int nt = 0; nt < 2; ++nt)
            #pragma unroll
            for (int c = 0; c < 4; ++c) {
                float x = s[nt][c] * scale;
                if (maskt) {
                    const int col = kbase + wn * 16 + nt * 8 + tig * 2 + (c & 1);
                    const int row = q0 + wm * 16 + g + 8 * (c >> 1);
                    if (col > row) x = -1e30f;
                }
                s[nt][c] = x;
            }

        float mx0 = fmaxf(fmaxf(s[0][0], s[0][1]), fmaxf(s[1][0], s[1][1]));
        float mx1 = fmaxf(fmaxf(s[0][2], s[0][3]), fmaxf(s[1][2], s[1][3]));
        mx0 = fmaxf(mx0, __shfl_xor_sync(0xffffffffu, mx0, 1));
        mx0 = fmaxf(mx0, __shfl_xor_sync(0xffffffffu, mx0, 2));
        mx1 = fmaxf(mx1, __shfl_xor_sync(0xffffffffu, mx1, 1));
        mx1 = fmaxf(mx1, __shfl_xor_sync(0xffffffffu, mx1, 2));
        if (tig == 0) {
            redmx[wn * 64 + wm * 16 + g]     = mx0;
            redmx[wn * 64 + wm * 16 + g + 8] = mx1;
        }
        __syncthreads();

        const int r0 = wm * 16 + g, r1 = r0 + 8;
        const float mg0 = fmaxf(redmx[r0], redmx[64 + r0]);
        const float mg1 = fmaxf(redmx[r1], redmx[64 + r1]);
        const float mn0 = fmaxf(m_i[0], mg0);
        const float mn1 = fmaxf(m_i[1], mg1);
        const float cr0 = __expf(m_i[0] - mn0);
        const float cr1 = __expf(m_i[1] - mn1);

        float sum0 = 0.f, sum1 = 0.f;
        #pragma unroll
        for (int nt = 0; nt < 2; ++nt) {
            const int keyc = wn * 16 + nt * 8 + tig * 2;
            float p0 = __expf(s[nt][0] - mn0);
            float p1 = __expf(s[nt][1] - mn0);
            float p2 = __expf(s[nt][2] - mn1);
            float p3 = __expf(s[nt][3] - mn1);
            sum0 += p0 + p1; sum1 += p2 + p3;
            __nv_bfloat162 l0, l1;
            __nv_bfloat162 h0 = split_pair(p0, p1, &l0);
            __nv_bfloat162 h1 = split_pair(p2, p3, &l1);
            *(__nv_bfloat162*)(sm + SP_HI + r0 * PP + keyc * 2) = h0;
            *(__nv_bfloat162*)(sm + SP_LO + r0 * PP + keyc * 2) = l0;
            *(__nv_bfloat162*)(sm + SP_HI + r1 * PP + keyc * 2) = h1;
            *(__nv_bfloat162*)(sm + SP_LO + r1 * PP + keyc * 2) = l1;
        }
        sum0 += __shfl_xor_sync(0xffffffffu, sum0, 1);
        sum0 += __shfl_xor_sync(0xffffffffu, sum0, 2);
        sum1 += __shfl_xor_sync(0xffffffffu, sum1, 1);
        sum1 += __shfl_xor_sync(0xffffffffu, sum1, 2);
        if (tig == 0) {
            redsm[wn * 64 + r0] = sum0;
            redsm[wn * 64 + r1] = sum1;
        }
        __syncthreads();

        l_i[0] = l_i[0] * cr0 + redsm[r0] + redsm[64 + r0];
        l_i[1] = l_i[1] * cr1 + redsm[r1] + redsm[64 + r1];
        m_i[0] = mn0; m_i[1] = mn1;
        #pragma unroll
        for (int nt = 0; nt < 8; ++nt) {
            o[nt][0] *= cr0; o[nt][1] *= cr0;
            o[nt][2] *= cr1; o[nt][3] *= cr1;
        }

        #pragma unroll
        for (int ks = 0; ks < 2; ++ks) {
            const unsigned ko  = ks * 32;
            const unsigned kvo = ks * 16 * QP;
            unsigned ph[4], pl[4], vh[4][4], vl[4][4];
            ldm4(ph, smem + SP_HI + aP + ko);
            ldm4(pl, smem + SP_LO + aP + ko);
            #pragma unroll
            for (int p = 0; p < 4; ++p) {
                ldm4t(vh[p], smem + SV_HI + bVt + kvo + p * 32);
                ldm4t(vl[p], smem + SV_LO + bVt + kvo + p * 32);
            }
            #pragma unroll
            for (int nt = 0; nt < 8; ++nt)
                mma_bf16(o[nt], ph, &vh[nt >> 1][(nt & 1) * 2]);
            #pragma unroll
            for (int nt = 0; nt < 8; ++nt)
                mma_bf16(o[nt], ph, &vl[nt >> 1][(nt & 1) * 2]);
            #pragma unroll
            for (int nt = 0; nt < 8; ++nt)
                mma_bf16(o[nt], pl, &vh[nt >> 1][(nt & 1) * 2]);
        }
    }

    const float inv0 = 1.f / l_i[0];
    const float inv1 = 1.f / l_i[1];
    const int row0 = q0 + wm * 16 + g;
    #pragma unroll
    for (int nt = 0; nt < 8; ++nt) {
        const int col = wn * 64 + nt * 8 + tig * 2;
        const size_t i0 = headoff + (size_t)row0 * HID + col;
        const size_t i1 = headoff + (size_t)(row0 + 8) * HID + col;
        __nv_bfloat162 l0, l1;
        __nv_bfloat162 h0 = split_pair(o[nt][0] * inv0, o[nt][1] * inv0, &l0);
        __nv_bfloat162 h1 = split_pair(o[nt][2] * inv1, o[nt][3] * inv1, &l1);
        *(__nv_bfloat162*)(ohi + i0) = h0;
        *(__nv_bfloat162*)(olo + i0) = l0;
        *(__nv_bfloat162*)(ohi + i1) = h1;
        *(__nv_bfloat162*)(olo + i1) = l1;
    }
}

// ---------------------------------------------------------------------------
extern "C" void kernel_launch(void* const* d_in, const int* in_sizes, int n_in,
                              void* d_out, int out_size)
{
    (void)in_sizes; (void)n_in; (void)out_size;
    const float* x  = (const float*)d_in[0];
    const float* fr = (const float*)d_in[1];
    const float* w0 = (const float*)d_in[2];
    const float* w1 = (const float*)d_in[3];
    const float* w2 = (const float*)d_in[4];
    const float* w3 = (const float*)d_in[5];
    float* out = (float*)d_out;

    __nv_bfloat16 *xhi, *xlo, *whi, *wlo;
    __nv_bfloat16 *qhi, *qlo, *khi, *klo, *vhi, *vlo, *aohi, *aolo;
    cudaGetSymbolAddress((void**)&xhi,  g_x_hi);
    cudaGetSymbolAddress((void**)&xlo,  g_x_lo);
    cudaGetSymbolAddress((void**)&whi,  g_w_hi);
    cudaGetSymbolAddress((void**)&wlo,  g_w_lo);
    cudaGetSymbolAddress((void**)&qhi,  g_q_hi);
    cudaGetSymbolAddress((void**)&qlo,  g_q_lo);
    cudaGetSymbolAddress((void**)&khi,  g_k_hi);
    cudaGetSymbolAddress((void**)&klo,  g_k_lo);
    cudaGetSymbolAddress((void**)&vhi,  g_v_hi);
    cudaGetSymbolAddress((void**)&vlo,  g_v_lo);
    cudaGetSymbolAddress((void**)&aohi, g_ao_hi);
    cudaGetSymbolAddress((void**)&aolo, g_ao_lo);

    cudaFuncSetAttribute(gemm_qkv,    cudaFuncAttributeMaxDynamicSharedMemorySize, GEMM_SMEM);
    cudaFuncSetAttribute(gemm_single, cudaFuncAttributeMaxDynamicSharedMemorySize, GEMM_SMEM);
    cudaFuncSetAttribute(attn_mma,    cudaFuncAttributeMaxDynamicSharedMemorySize, ATTN_SMEM);

    split_all<<<(TOT4 + 255) / 256, 256>>>(x, w0, w1, w2, w3, xhi, xlo, whi, wlo);

    dim3 gqkv(HID / 128, MROWS / 128, 3);
    gemm_qkv<<<gqkv, 256, GEMM_SMEM>>>(xhi, xlo, whi, wlo,
                                       qhi, qlo, khi, klo, vhi, vlo, fr);

    attn_mma<<<dim3(SEQ / 64, BATCH * NHEAD), 256, ATTN_SMEM>>>(
        qhi, qlo, khi, klo, vhi, vlo, aohi, aolo);

    dim3 gg(HID / 128, MROWS / 128);
    gemm_single<<<gg, 256, GEMM_SMEM>>>(aohi, aolo, whi + 3 * (size_t)HID * HID,
                                        wlo + 3 * (size_t)HID * HID, out);
}